// round 1
// baseline (speedup 1.0000x reference)
#include <cuda_runtime.h>
#include <math.h>

#define B_ 4
#define S_ 2048
#define N_ 2048
#define D_ 1024
#define H_ 16
#define HD_ 64
#define EPS_ 1e-5f

// Scratch (allocation-free rule: __device__ globals)
__device__ float g_kn[B_ * N_ * HD_];                 // normalized K: 2 MB
__device__ float g_x[(size_t)B_ * S_ * D_];           // attention out, (B,S,D) layout: 33.5 MB
__device__ float g_xn[(size_t)B_ * S_ * D_];          // LN(x): 33.5 MB

// ---------------------------------------------------------------------------
// Kernel 1: LayerNorm over K rows (HD=64). One warp per row.
// ---------------------------------------------------------------------------
__global__ __launch_bounds__(256) void ln_k_kernel(
    const float* __restrict__ xk, const float* __restrict__ w,
    const float* __restrict__ bb)
{
    int row  = blockIdx.x * 8 + (threadIdx.x >> 5);
    int lane = threadIdx.x & 31;
    const float* r = xk + (size_t)row * HD_;
    float a0 = r[lane], a1 = r[lane + 32];
    float s = a0 + a1;
    #pragma unroll
    for (int off = 16; off; off >>= 1) s += __shfl_xor_sync(0xffffffffu, s, off);
    float mean = s * (1.f / 64.f);
    float d0 = a0 - mean, d1 = a1 - mean;
    float vv = d0 * d0 + d1 * d1;
    #pragma unroll
    for (int off = 16; off; off >>= 1) vv += __shfl_xor_sync(0xffffffffu, vv, off);
    float inv = rsqrtf(vv * (1.f / 64.f) + EPS_);
    g_kn[(size_t)row * HD_ + lane]      = d0 * inv * w[lane]      + bb[lane];
    g_kn[(size_t)row * HD_ + lane + 32] = d1 * inv * w[lane + 32] + bb[lane + 32];
}

// ---------------------------------------------------------------------------
// Kernel 2: Flash attention with fused Q-layernorm.
// Block = 256 threads (16x16), computes a 64-query tile for one (b, h).
// Writes output directly in (B, S, D) transposed layout into g_x.
// Dynamic smem: qs[64][64] + kt[64][65] + vs[64][64] + ps[64][64] = 65792 B.
// ---------------------------------------------------------------------------
#define ATTN_SMEM_BYTES ((4096 + 4160 + 4096 + 4096) * 4)

__global__ __launch_bounds__(256, 1) void attn_kernel(
    const float* __restrict__ xq, const float* __restrict__ xv,
    const float* __restrict__ qnw, const float* __restrict__ qnb)
{
    extern __shared__ float sm[];
    float (*qs)[64] = (float(*)[64])(sm);
    float (*kt)[65] = (float(*)[65])(sm + 4096);
    float (*vs)[64] = (float(*)[64])(sm + 4096 + 4160);
    float (*ps)[64] = (float(*)[64])(sm + 4096 + 4160 + 4096);

    int b = blockIdx.z, h = blockIdx.y, st = blockIdx.x;
    int tid = threadIdx.x;
    int tx = tid & 15, ty = tid >> 4;

    // q[b,h,s,hd] = xq_flat[b*S*D + h*S*HD + s*HD + hd]  (reshape, no transpose)
    const float* qbase = xq + (size_t)b * S_ * D_ + (size_t)h * S_ * HD_
                            + (size_t)st * 64 * HD_;
    for (int i = tid; i < 64 * 64; i += 256)
        qs[i >> 6][i & 63] = qbase[i];
    __syncthreads();

    // Fused Q layernorm (+ scale HD^-0.5), one thread per row
    if (tid < 64) {
        float m = 0.f;
        #pragma unroll 16
        for (int d = 0; d < 64; d++) m += qs[tid][d];
        m *= (1.f / 64.f);
        float v = 0.f;
        #pragma unroll 16
        for (int d = 0; d < 64; d++) { float t = qs[tid][d] - m; v += t * t; }
        float inv = rsqrtf(v * (1.f / 64.f) + EPS_);
        const float scale = 0.125f;  // 64^-0.5
        #pragma unroll 16
        for (int d = 0; d < 64; d++)
            qs[tid][d] = ((qs[tid][d] - m) * inv * qnw[d] + qnb[d]) * scale;
    }
    __syncthreads();

    float o[4][4] = {};
    float mrow[4] = {-INFINITY, -INFINITY, -INFINITY, -INFINITY};
    float lrow[4] = {};

    const float* kb = g_kn + (size_t)b * N_ * HD_;
    const float* vb = xv   + (size_t)b * N_ * HD_;

    for (int n0 = 0; n0 < N_; n0 += 64) {
        // Stage K (transposed, padded -> conflict-free) and V tiles
        for (int i = tid; i < 64 * 64; i += 256) {
            int r = i >> 6, d = i & 63;
            kt[d][r] = kb[(size_t)(n0 + r) * HD_ + d];
            vs[r][d] = vb[(size_t)(n0 + r) * HD_ + d];
        }
        __syncthreads();

        // Scores: sc[i][j] = dot(q_row, k_col)
        float sc[4][4] = {};
        #pragma unroll 8
        for (int d = 0; d < 64; d++) {
            float qv[4], kv[4];
            #pragma unroll
            for (int i = 0; i < 4; i++) qv[i] = qs[ty * 4 + i][d];
            #pragma unroll
            for (int j = 0; j < 4; j++) kv[j] = kt[d][tx * 4 + j];
            #pragma unroll
            for (int i = 0; i < 4; i++)
                #pragma unroll
                for (int j = 0; j < 4; j++) sc[i][j] += qv[i] * kv[j];
        }

        // Online softmax (row stats reduced across the 16 tx lanes)
        #pragma unroll
        for (int i = 0; i < 4; i++) {
            float mx = fmaxf(fmaxf(sc[i][0], sc[i][1]), fmaxf(sc[i][2], sc[i][3]));
            #pragma unroll
            for (int off = 8; off; off >>= 1)
                mx = fmaxf(mx, __shfl_xor_sync(0xffffffffu, mx, off, 16));
            float mnew  = fmaxf(mrow[i], mx);
            float alpha = __expf(mrow[i] - mnew);
            float psum = 0.f;
            #pragma unroll
            for (int j = 0; j < 4; j++) {
                float p = __expf(sc[i][j] - mnew);
                ps[ty * 4 + i][tx * 4 + j] = p;
                psum += p;
            }
            #pragma unroll
            for (int off = 8; off; off >>= 1)
                psum += __shfl_xor_sync(0xffffffffu, psum, off, 16);
            lrow[i] = lrow[i] * alpha + psum;
            mrow[i] = mnew;
            #pragma unroll
            for (int j = 0; j < 4; j++) o[i][j] *= alpha;
        }
        __syncthreads();

        // O += P @ V
        #pragma unroll 8
        for (int k = 0; k < 64; k++) {
            float pv[4], vv[4];
            #pragma unroll
            for (int i = 0; i < 4; i++) pv[i] = ps[ty * 4 + i][k];
            #pragma unroll
            for (int j = 0; j < 4; j++) vv[j] = vs[k][tx * 4 + j];
            #pragma unroll
            for (int i = 0; i < 4; i++)
                #pragma unroll
                for (int j = 0; j < 4; j++) o[i][j] += pv[i] * vv[j];
        }
        __syncthreads();
    }

    // Write in transposed (B, S, D) layout: x[b][s][h*64 + c]
    float* xo = g_x + (size_t)b * S_ * D_ + (size_t)(st * 64) * D_ + (size_t)h * 64;
    #pragma unroll
    for (int i = 0; i < 4; i++) {
        float rinv = 1.f / lrow[i];
        #pragma unroll
        for (int j = 0; j < 4; j++)
            xo[(size_t)(ty * 4 + i) * D_ + tx * 4 + j] = o[i][j] * rinv;
    }
}

// ---------------------------------------------------------------------------
// Kernel 3: LayerNorm over D=1024, one block (256 thr) per row, float4 path.
// ---------------------------------------------------------------------------
__global__ __launch_bounds__(256) void ln_d_kernel(
    const float* __restrict__ w, const float* __restrict__ bb)
{
    __shared__ float red[8];
    int row = blockIdx.x;
    int tid = threadIdx.x;
    const float4* r4 = (const float4*)(g_x + (size_t)row * D_);
    float4 v = r4[tid];

    float s = v.x + v.y + v.z + v.w;
    #pragma unroll
    for (int off = 16; off; off >>= 1) s += __shfl_xor_sync(0xffffffffu, s, off);
    if ((tid & 31) == 0) red[tid >> 5] = s;
    __syncthreads();
    float tot = red[0] + red[1] + red[2] + red[3] + red[4] + red[5] + red[6] + red[7];
    float mean = tot * (1.f / D_);

    float dx = v.x - mean, dy = v.y - mean, dz = v.z - mean, dw = v.w - mean;
    float ss = dx * dx + dy * dy + dz * dz + dw * dw;
    __syncthreads();
    #pragma unroll
    for (int off = 16; off; off >>= 1) ss += __shfl_xor_sync(0xffffffffu, ss, off);
    if ((tid & 31) == 0) red[tid >> 5] = ss;
    __syncthreads();
    float vtot = red[0] + red[1] + red[2] + red[3] + red[4] + red[5] + red[6] + red[7];
    float inv = rsqrtf(vtot * (1.f / D_) + EPS_);

    float4 wv = ((const float4*)w)[tid];
    float4 bv = ((const float4*)bb)[tid];
    float4 o;
    o.x = dx * inv * wv.x + bv.x;
    o.y = dy * inv * wv.y + bv.y;
    o.z = dz * inv * wv.z + bv.z;
    o.w = dw * inv * wv.w + bv.w;
    ((float4*)(g_xn + (size_t)row * D_))[tid] = o;
}

// ---------------------------------------------------------------------------
// Kernel 4: out = xn @ proj_w^T   (NT GEMM, both K-contiguous)
// M=8192, N=1024, K=1024. 64x64 tiles, 4x4 micro-tiles.
// ---------------------------------------------------------------------------
__global__ __launch_bounds__(256) void gemm_nt_kernel(
    const float* __restrict__ W, float* __restrict__ C)
{
    __shared__ float as[64][64];
    __shared__ float wt[64][65];
    int ct = blockIdx.x, rt = blockIdx.y;
    int tid = threadIdx.x, tx = tid & 15, ty = tid >> 4;
    float acc[4][4] = {};

    const float* Ab = g_xn + (size_t)rt * 64 * D_;
    const float* Wb = W    + (size_t)ct * 64 * D_;

    for (int k0 = 0; k0 < D_; k0 += 64) {
        for (int i = tid; i < 64 * 64; i += 256) {
            int r = i >> 6, k = i & 63;
            as[r][k] = Ab[(size_t)r * D_ + k0 + k];
            wt[k][r] = Wb[(size_t)r * D_ + k0 + k];
        }
        __syncthreads();
        #pragma unroll 8
        for (int k = 0; k < 64; k++) {
            float av[4], wv[4];
            #pragma unroll
            for (int i = 0; i < 4; i++) av[i] = as[ty * 4 + i][k];
            #pragma unroll
            for (int j = 0; j < 4; j++) wv[j] = wt[k][tx * 4 + j];
            #pragma unroll
            for (int i = 0; i < 4; i++)
                #pragma unroll
                for (int j = 0; j < 4; j++) acc[i][j] += av[i] * wv[j];
        }
        __syncthreads();
    }
    float* Cb = C + (size_t)(rt * 64) * D_ + ct * 64;
    #pragma unroll
    for (int i = 0; i < 4; i++)
        #pragma unroll
        for (int j = 0; j < 4; j++)
            Cb[(size_t)(ty * 4 + i) * D_ + tx * 4 + j] = acc[i][j];
}

// ---------------------------------------------------------------------------
extern "C" void kernel_launch(void* const* d_in, const int* in_sizes, int n_in,
                              void* d_out, int out_size)
{
    const float* x_q    = (const float*)d_in[0];
    const float* x_k    = (const float*)d_in[1];
    const float* x_v    = (const float*)d_in[2];
    const float* qn_w   = (const float*)d_in[3];
    const float* qn_b   = (const float*)d_in[4];
    const float* kn_w   = (const float*)d_in[5];
    const float* kn_b   = (const float*)d_in[6];
    const float* n_w    = (const float*)d_in[7];
    const float* n_b    = (const float*)d_in[8];
    const float* proj_w = (const float*)d_in[9];
    float* out = (float*)d_out;

    cudaFuncSetAttribute(attn_kernel, cudaFuncAttributeMaxDynamicSharedMemorySize,
                         ATTN_SMEM_BYTES);

    // 1) LN(K) -> g_kn
    ln_k_kernel<<<(B_ * N_) / 8, 256>>>(x_k, kn_w, kn_b);
    // 2) flash attention (fused Q-LN), writes transposed layout -> g_x
    attn_kernel<<<dim3(S_ / 64, H_, B_), 256, ATTN_SMEM_BYTES>>>(x_q, x_v, qn_w, qn_b);
    // 3) LN over D -> g_xn
    ln_d_kernel<<<B_ * S_, 256>>>(n_w, n_b);
    // 4) proj GEMM -> out
    gemm_nt_kernel<<<dim3(D_ / 64, (B_ * S_) / 64), 256>>>(proj_w, out);
}

// round 3
// speedup vs baseline: 4.7169x; 4.7169x over previous
#include <cuda_runtime.h>
#include <cstdint>
#include <math.h>

#define B_ 4
#define S_ 2048
#define N_ 2048
#define D_ 1024
#define H_ 16
#define HD_ 64
#define EPS_ 1e-5f

// tcgen05 requires the arch-specific feature set (sm_103a / sm_100a).
#ifndef __CUDA_ARCH__
  #define HAS_TC 1
#elif defined(__CUDA_ARCH_FEAT_SM103_ALL) || defined(__CUDA_ARCH_FEAT_SM100_ALL) || \
      defined(__CUDA_ARCH_FEAT_SM101_ALL)
  #define HAS_TC 1
#else
  #define HAS_TC 0
#endif

// Scratch
__device__ float g_kn[B_ * N_ * HD_];
__device__ float g_x[(size_t)B_ * S_ * D_];
__device__ float g_xn[(size_t)B_ * S_ * D_];

// ---------------------------------------------------------------------------
// PTX helpers
// ---------------------------------------------------------------------------
__device__ __forceinline__ uint32_t smem_u32(const void* p) {
    uint32_t a;
    asm("{ .reg .u64 t; cvta.to.shared.u64 t, %1; cvt.u32.u64 %0, t; }"
        : "=r"(a) : "l"(p));
    return a;
}
__device__ __forceinline__ uint32_t elect1() {
    uint32_t r;
    asm volatile("{ .reg .pred p; elect.sync _|p, 0xFFFFFFFF; selp.b32 %0, 1, 0, p; }"
                 : "=r"(r));
    return r;
}
__device__ __forceinline__ float to_tf32(float x) {
    float r; asm("cvt.rna.tf32.f32 %0, %1;" : "=f"(r) : "f"(x)); return r;
}

#define SWZ(x) ((uint32_t)(x) ^ ((((uint32_t)(x)) >> 3) & 0x70u))

static constexpr uint64_t DESC_BASE_SW128 =
    (uint64_t(2) << 61) | (uint64_t(1) << 46) | (uint64_t(64) << 32) | (uint64_t(1) << 16);
#define MK_DESC(addr) (DESC_BASE_SW128 | ((uint64_t)((addr) >> 4) & 0x3FFFull))

// idesc: c=F32(1)@4, a=TF32(2)@7, b=TF32(2)@10, N/8@17, M/16@24
#define IDESC_TF32(Ncols) \
    ((1u << 4) | (2u << 7) | (2u << 10) | (((Ncols) / 8u) << 17) | (8u << 24))

#if HAS_TC
__device__ __forceinline__ void mma_tf32_ss(uint32_t d_tmem, uint64_t a_desc,
                                            uint64_t b_desc, uint32_t idesc, bool acc) {
    uint32_t en = acc ? 1u : 0u;
    asm volatile(
        "{\n\t.reg .pred p;\n\tsetp.ne.u32 p, %4, 0;\n\t"
        "tcgen05.mma.cta_group::1.kind::tf32 [%0], %1, %2, %3, {%5, %5, %5, %5}, p;\n\t}"
        :: "r"(d_tmem), "l"(a_desc), "l"(b_desc), "r"(idesc), "r"(en), "r"(0u)
        : "memory");
}

#define TC_ALLOC(slot, n) \
    asm volatile("tcgen05.alloc.cta_group::1.sync.aligned.shared::cta.b32 [%0], %1;" \
                 :: "r"(slot), "r"((uint32_t)(n)) : "memory")
#define TC_RELINQ() \
    asm volatile("tcgen05.relinquish_alloc_permit.cta_group::1.sync.aligned;")
#define TC_DEALLOC(tb, n) \
    asm volatile("tcgen05.dealloc.cta_group::1.sync.aligned.b32 %0, %1;" :: "r"(tb), "r"((uint32_t)(n)))
#define TC_COMMIT(mbar) \
    asm volatile("tcgen05.commit.cta_group::1.mbarrier::arrive::one.shared::cluster.b64 [%0];" \
                 :: "r"(mbar) : "memory")
#define TC_FENCE_BEFORE() asm volatile("tcgen05.fence::before_thread_sync;" ::: "memory")
#define TC_FENCE_AFTER()  asm volatile("tcgen05.fence::after_thread_sync;" ::: "memory")
#define TC_WAIT_LD()      asm volatile("tcgen05.wait::ld.sync.aligned;" ::: "memory")
#define FENCE_ASYNC()     asm volatile("fence.proxy.async.shared::cta;" ::: "memory")

#define MBAR_INIT(a, c) \
    asm volatile("mbarrier.init.shared.b64 [%0], %1;" :: "r"(a), "r"((uint32_t)(c)) : "memory")
#define MBAR_WAIT(a, par) do { \
    uint32_t _m = (a); uint32_t _p = (par); uint32_t _d; \
    asm volatile("{\n\t.reg .pred p;\n\t" \
        "mbarrier.try_wait.parity.acquire.cta.shared::cta.b64 p, [%1], %2;\n\t" \
        "selp.b32 %0, 1, 0, p;\n\t}" : "=r"(_d) : "r"(_m), "r"(_p) : "memory"); \
    if (!_d) { \
        asm volatile("{\n\t.reg .pred P1;\n\tWL_%=:\n\t" \
            "mbarrier.try_wait.parity.acquire.cta.shared::cta.b64 P1, [%0], %1, 0x989680;\n\t" \
            "@P1 bra.uni WD_%=;\n\tbra.uni WL_%=;\n\tWD_%=:\n\t}" \
            :: "r"(_m), "r"(_p) : "memory"); \
    } } while (0)

#define LDTM_X32(r, a) \
    asm volatile("tcgen05.ld.sync.aligned.32x32b.x32.b32 " \
        "{%0,%1,%2,%3,%4,%5,%6,%7,%8,%9,%10,%11,%12,%13,%14,%15," \
        "%16,%17,%18,%19,%20,%21,%22,%23,%24,%25,%26,%27,%28,%29,%30,%31}, [%32];" \
        : "=r"((r)[0]), "=r"((r)[1]), "=r"((r)[2]), "=r"((r)[3]), \
          "=r"((r)[4]), "=r"((r)[5]), "=r"((r)[6]), "=r"((r)[7]), \
          "=r"((r)[8]), "=r"((r)[9]), "=r"((r)[10]), "=r"((r)[11]), \
          "=r"((r)[12]), "=r"((r)[13]), "=r"((r)[14]), "=r"((r)[15]), \
          "=r"((r)[16]), "=r"((r)[17]), "=r"((r)[18]), "=r"((r)[19]), \
          "=r"((r)[20]), "=r"((r)[21]), "=r"((r)[22]), "=r"((r)[23]), \
          "=r"((r)[24]), "=r"((r)[25]), "=r"((r)[26]), "=r"((r)[27]), \
          "=r"((r)[28]), "=r"((r)[29]), "=r"((r)[30]), "=r"((r)[31]) \
        : "r"(a))
#endif  // HAS_TC

// ---------------------------------------------------------------------------
// Kernel 1: LayerNorm over K rows (HD=64). One warp per row. (both paths)
// ---------------------------------------------------------------------------
__global__ __launch_bounds__(256) void ln_k_kernel(
    const float* __restrict__ xk, const float* __restrict__ w,
    const float* __restrict__ bb)
{
    int row  = blockIdx.x * 8 + (threadIdx.x >> 5);
    int lane = threadIdx.x & 31;
    const float* r = xk + (size_t)row * HD_;
    float a0 = r[lane], a1 = r[lane + 32];
    float s = a0 + a1;
    #pragma unroll
    for (int off = 16; off; off >>= 1) s += __shfl_xor_sync(0xffffffffu, s, off);
    float mean = s * (1.f / 64.f);
    float d0 = a0 - mean, d1 = a1 - mean;
    float vv = d0 * d0 + d1 * d1;
    #pragma unroll
    for (int off = 16; off; off >>= 1) vv += __shfl_xor_sync(0xffffffffu, vv, off);
    float inv = rsqrtf(vv * (1.f / 64.f) + EPS_);
    g_kn[(size_t)row * HD_ + lane]      = d0 * inv * w[lane]      + bb[lane];
    g_kn[(size_t)row * HD_ + lane + 32] = d1 * inv * w[lane + 32] + bb[lane + 32];
}

// ---------------------------------------------------------------------------
// Kernel 2 (fast): tcgen05 tf32 attention. 256 thr, 128-query tile per CTA.
// ---------------------------------------------------------------------------
#define AQ 1024
#define AK 33792
#define AV 66560
#define AP 99328
#define ALC 164864
#define APT 165376
#define ATTN_SMEM (APT + 1024 + 256)

__global__ __launch_bounds__(256, 1) void attn_tc_kernel(
    const float* __restrict__ xq, const float* __restrict__ xv,
    const float* __restrict__ qnw, const float* __restrict__ qnb)
{
#if HAS_TC
    extern __shared__ char smem[];
    uint32_t sb = smem_u32(smem);
    int tid = threadIdx.x, wid = tid >> 5, lane = tid & 31;
    int b = blockIdx.z, h = blockIdx.y, st = blockIdx.x;

    if (wid == 0) { TC_ALLOC(sb, 256); TC_RELINQ(); }
    if (tid == 0) MBAR_INIT(sb + 8, 1);
    if (tid < 128) *(float*)(smem + ALC + tid * 4) = 0.f;
    __syncthreads();
    uint32_t tb;
    asm volatile("ld.shared.b32 %0, [%1];" : "=r"(tb) : "r"(sb));

    // ---- Q load + LN + stage ----
    if (tid < 128) {
        const float* qr = xq + (size_t)b * S_ * D_ + (size_t)h * S_ * HD_
                             + (size_t)(st * 128 + tid) * 64;
        float4 v[16];
        #pragma unroll
        for (int i = 0; i < 16; i++) v[i] = ((const float4*)qr)[i];
        float m = 0.f;
        #pragma unroll
        for (int i = 0; i < 16; i++) m += v[i].x + v[i].y + v[i].z + v[i].w;
        m *= (1.f / 64.f);
        float var = 0.f;
        #pragma unroll
        for (int i = 0; i < 16; i++) {
            float a = v[i].x - m, bq = v[i].y - m, c = v[i].z - m, d = v[i].w - m;
            var += a * a + bq * bq + c * c + d * d;
        }
        float inv = rsqrtf(var * (1.f / 64.f) + EPS_) * 0.125f;
        #pragma unroll
        for (int i = 0; i < 16; i++) {
            float4 w4 = ((const float4*)qnw)[i];
            float4 b4 = ((const float4*)qnb)[i];
            float4 o;
            o.x = to_tf32((v[i].x - m) * inv * w4.x + b4.x * 0.125f);
            o.y = to_tf32((v[i].y - m) * inv * w4.y + b4.y * 0.125f);
            o.z = to_tf32((v[i].z - m) * inv * w4.z + b4.z * 0.125f);
            o.w = to_tf32((v[i].w - m) * inv * w4.w + b4.w * 0.125f);
            *(float4*)(smem + AQ + (i >> 3) * 16384 + SWZ(tid * 128 + (i & 7) * 16)) = o;
        }
    }

    const uint32_t idq  = IDESC_TF32(128);
    const uint32_t idpv = IDESC_TF32(64);
    int ph = 0;

    for (int it = 0; it < 16; it++) {
        int n0 = it * 128;
        const float* kb = g_kn + (size_t)b * N_ * HD_ + (size_t)n0 * 64;
        const float* vb = xv   + (size_t)b * N_ * HD_ + (size_t)n0 * 64;
        #pragma unroll
        for (int rep = 0; rep < 8; rep++) {
            int idx = tid + rep * 256;          // 0..2047
            int nl = idx >> 4, d4 = idx & 15;
            float4 kv = ((const float4*)(kb + nl * 64))[d4];
            kv.x = to_tf32(kv.x); kv.y = to_tf32(kv.y);
            kv.z = to_tf32(kv.z); kv.w = to_tf32(kv.w);
            *(float4*)(smem + AK + (d4 >> 3) * 16384 + SWZ(nl * 128 + (d4 & 7) * 16)) = kv;
            float4 vv = ((const float4*)(vb + nl * 64))[d4];
            char* vtc = smem + AV + (nl >> 5) * 8192;
            int np = nl & 31;
            *(float*)(vtc + SWZ((d4 * 4 + 0) * 128 + np * 4)) = to_tf32(vv.x);
            *(float*)(vtc + SWZ((d4 * 4 + 1) * 128 + np * 4)) = to_tf32(vv.y);
            *(float*)(vtc + SWZ((d4 * 4 + 2) * 128 + np * 4)) = to_tf32(vv.z);
            *(float*)(vtc + SWZ((d4 * 4 + 3) * 128 + np * 4)) = to_tf32(vv.w);
        }
        __syncthreads();

        if (wid == 0 && elect1()) {
            FENCE_ASYNC();
            #pragma unroll
            for (int c = 0; c < 2; c++) {
                uint64_t ad = MK_DESC(sb + AQ + c * 16384);
                uint64_t bd = MK_DESC(sb + AK + c * 16384);
                #pragma unroll
                for (int ks = 0; ks < 4; ks++)
                    mma_tf32_ss(tb, ad + ks * 2, bd + ks * 2, idq, !(c == 0 && ks == 0));
            }
            TC_COMMIT(sb + 8);
        }
        MBAR_WAIT(sb + 8, ph); ph ^= 1;
        TC_FENCE_AFTER();

        // ---- softmax: warp -> 32 rows x two 32-col sub-blocks ----
        int half = wid >> 2;
        int row = (wid & 3) * 32 + lane;
        float psum = 0.f;
        #pragma unroll
        for (int sbk = 0; sbk < 2; sbk++) {
            uint32_t r[32];
            LDTM_X32(r, tb + half * 64 + sbk * 32);
            TC_WAIT_LD();
            char* pb = smem + AP + (half * 2 + sbk) * 16384;
            #pragma unroll
            for (int j4 = 0; j4 < 8; j4++) {
                float4 o4;
                o4.x = to_tf32(__expf(__uint_as_float(r[j4 * 4 + 0])));
                o4.y = to_tf32(__expf(__uint_as_float(r[j4 * 4 + 1])));
                o4.z = to_tf32(__expf(__uint_as_float(r[j4 * 4 + 2])));
                o4.w = to_tf32(__expf(__uint_as_float(r[j4 * 4 + 3])));
                psum += o4.x + o4.y + o4.z + o4.w;
                *(float4*)(pb + SWZ(row * 128 + j4 * 16)) = o4;
            }
        }
        *(float*)(smem + APT + (half * 128 + row) * 4) = psum;
        TC_FENCE_BEFORE();
        __syncthreads();

        if (tid < 128) {
            float* la = (float*)(smem + ALC);
            la[tid] += *(float*)(smem + APT + tid * 4)
                     + *(float*)(smem + APT + 512 + tid * 4);
        }
        if (wid == 0 && elect1()) {
            FENCE_ASYNC();
            #pragma unroll
            for (int c = 0; c < 4; c++) {
                uint64_t ad = MK_DESC(sb + AP + c * 16384);
                uint64_t bd = MK_DESC(sb + AV + c * 8192);
                #pragma unroll
                for (int ks = 0; ks < 4; ks++)
                    mma_tf32_ss(tb + 128, ad + ks * 2, bd + ks * 2, idpv,
                                !(it == 0 && c == 0 && ks == 0));
            }
            TC_COMMIT(sb + 8);
        }
        MBAR_WAIT(sb + 8, ph); ph ^= 1;
    }
    TC_FENCE_AFTER();

    // ---- epilogue ----
    if (wid < 4) {
        int row = wid * 32 + lane;
        uint32_t o0[32], o1[32];
        LDTM_X32(o0, tb + 128);
        LDTM_X32(o1, tb + 160);
        TC_WAIT_LD();
        float rin = 1.f / *(float*)(smem + ALC + row * 4);
        float* od = g_x + (size_t)b * S_ * D_ + (size_t)(st * 128 + row) * D_ + h * 64;
        #pragma unroll
        for (int j4 = 0; j4 < 8; j4++) {
            ((float4*)od)[j4] = make_float4(__uint_as_float(o0[j4 * 4 + 0]) * rin,
                                            __uint_as_float(o0[j4 * 4 + 1]) * rin,
                                            __uint_as_float(o0[j4 * 4 + 2]) * rin,
                                            __uint_as_float(o0[j4 * 4 + 3]) * rin);
            ((float4*)od)[8 + j4] = make_float4(__uint_as_float(o1[j4 * 4 + 0]) * rin,
                                                __uint_as_float(o1[j4 * 4 + 1]) * rin,
                                                __uint_as_float(o1[j4 * 4 + 2]) * rin,
                                                __uint_as_float(o1[j4 * 4 + 3]) * rin);
        }
    }
    TC_FENCE_BEFORE();
    __syncthreads();
    if (wid == 0) TC_DEALLOC(tb, 256);
#endif
}

// ---------------------------------------------------------------------------
// Kernel 3: LayerNorm over D=1024 (both paths)
// ---------------------------------------------------------------------------
__global__ __launch_bounds__(256) void ln_d_kernel(
    const float* __restrict__ w, const float* __restrict__ bb)
{
    __shared__ float red[8];
    int row = blockIdx.x;
    int tid = threadIdx.x;
    const float4* r4 = (const float4*)(g_x + (size_t)row * D_);
    float4 v = r4[tid];

    float s = v.x + v.y + v.z + v.w;
    #pragma unroll
    for (int off = 16; off; off >>= 1) s += __shfl_xor_sync(0xffffffffu, s, off);
    if ((tid & 31) == 0) red[tid >> 5] = s;
    __syncthreads();
    float tot = red[0] + red[1] + red[2] + red[3] + red[4] + red[5] + red[6] + red[7];
    float mean = tot * (1.f / D_);

    float dx = v.x - mean, dy = v.y - mean, dz = v.z - mean, dw = v.w - mean;
    float ss = dx * dx + dy * dy + dz * dz + dw * dw;
    __syncthreads();
    #pragma unroll
    for (int off = 16; off; off >>= 1) ss += __shfl_xor_sync(0xffffffffu, ss, off);
    if ((tid & 31) == 0) red[tid >> 5] = ss;
    __syncthreads();
    float vtot = red[0] + red[1] + red[2] + red[3] + red[4] + red[5] + red[6] + red[7];
    float inv = rsqrtf(vtot * (1.f / D_) + EPS_);

    float4 wv = ((const float4*)w)[tid];
    float4 bv = ((const float4*)bb)[tid];
    float4 o;
    o.x = dx * inv * wv.x + bv.x;
    o.y = dy * inv * wv.y + bv.y;
    o.z = dz * inv * wv.z + bv.z;
    o.w = dw * inv * wv.w + bv.w;
    ((float4*)(g_xn + (size_t)row * D_))[tid] = o;
}

// ---------------------------------------------------------------------------
// Kernel 4 (fast): tf32 tcgen05 GEMM  C = g_xn @ W^T, 128x128 tiles
// ---------------------------------------------------------------------------
#define GA 1024
#define GB 33792
#define GEMM_SMEM (1024 + 65536 + 256)

__global__ __launch_bounds__(256, 1) void gemm_tc_kernel(
    const float* __restrict__ W, float* __restrict__ C)
{
#if HAS_TC
    extern __shared__ char smem[];
    uint32_t sb = smem_u32(smem);
    int tid = threadIdx.x, wid = tid >> 5, lane = tid & 31;
    int n0 = blockIdx.x * 128, m0 = blockIdx.y * 128;

    if (wid == 0) { TC_ALLOC(sb, 128); TC_RELINQ(); }
    if (tid == 0) { MBAR_INIT(sb + 8, 1); MBAR_INIT(sb + 16, 1); }
    __syncthreads();
    uint32_t tb;
    asm volatile("ld.shared.b32 %0, [%1];" : "=r"(tb) : "r"(sb));

    const uint32_t idc = IDESC_TF32(128);
    int ph0 = 0, ph1 = 0;

    for (int c = 0; c < 32; c++) {
        int bs = c & 1;
        if (c >= 2) {
            if (bs == 0) { MBAR_WAIT(sb + 8, ph0);  ph0 ^= 1; }
            else         { MBAR_WAIT(sb + 16, ph1); ph1 ^= 1; }
        }
        int k0 = c * 32;
        char* abuf = smem + GA + bs * 16384;
        char* bbuf = smem + GB + bs * 16384;
        #pragma unroll
        for (int rep = 0; rep < 4; rep++) {
            int idx = tid + rep * 256;          // 0..1023
            int r = idx >> 3, k4 = idx & 7;
            float4 a4 = *(const float4*)(g_xn + (size_t)(m0 + r) * D_ + k0 + k4 * 4);
            a4.x = to_tf32(a4.x); a4.y = to_tf32(a4.y);
            a4.z = to_tf32(a4.z); a4.w = to_tf32(a4.w);
            *(float4*)(abuf + SWZ(r * 128 + k4 * 16)) = a4;
            float4 b4 = *(const float4*)(W + (size_t)(n0 + r) * D_ + k0 + k4 * 4);
            b4.x = to_tf32(b4.x); b4.y = to_tf32(b4.y);
            b4.z = to_tf32(b4.z); b4.w = to_tf32(b4.w);
            *(float4*)(bbuf + SWZ(r * 128 + k4 * 16)) = b4;
        }
        __syncthreads();
        if (wid == 0 && elect1()) {
            FENCE_ASYNC();
            uint64_t ad = MK_DESC(sb + GA + bs * 16384);
            uint64_t bd = MK_DESC(sb + GB + bs * 16384);
            #pragma unroll
            for (int ks = 0; ks < 4; ks++)
                mma_tf32_ss(tb, ad + ks * 2, bd + ks * 2, idc, !(c == 0 && ks == 0));
            TC_COMMIT(sb + 8 + bs * 8);
        }
    }
    MBAR_WAIT(sb + 8, ph0);
    MBAR_WAIT(sb + 16, ph1);
    TC_FENCE_AFTER();

    int half = wid >> 2;
    int row = (wid & 3) * 32 + lane;
    uint32_t o0[32], o1[32];
    LDTM_X32(o0, tb + half * 64);
    LDTM_X32(o1, tb + half * 64 + 32);
    TC_WAIT_LD();
    float* cd = C + (size_t)(m0 + row) * D_ + n0 + half * 64;
    #pragma unroll
    for (int j4 = 0; j4 < 8; j4++) {
        ((float4*)cd)[j4] = make_float4(__uint_as_float(o0[j4 * 4 + 0]),
                                        __uint_as_float(o0[j4 * 4 + 1]),
                                        __uint_as_float(o0[j4 * 4 + 2]),
                                        __uint_as_float(o0[j4 * 4 + 3]));
        ((float4*)cd)[8 + j4] = make_float4(__uint_as_float(o1[j4 * 4 + 0]),
                                            __uint_as_float(o1[j4 * 4 + 1]),
                                            __uint_as_float(o1[j4 * 4 + 2]),
                                            __uint_as_float(o1[j4 * 4 + 3]));
    }
    TC_FENCE_BEFORE();
    __syncthreads();
    if (wid == 0) TC_DEALLOC(tb, 128);
#endif
}

// ---------------------------------------------------------------------------
// Fallback kernels (round-1, proven correct)
// ---------------------------------------------------------------------------
#define ATTN_FB_SMEM ((4096 + 4160 + 4096 + 4096) * 4)

__global__ __launch_bounds__(256, 1) void attn_fb_kernel(
    const float* __restrict__ xq, const float* __restrict__ xv,
    const float* __restrict__ qnw, const float* __restrict__ qnb)
{
    extern __shared__ float sm[];
    float (*qs)[64] = (float(*)[64])(sm);
    float (*kt)[65] = (float(*)[65])(sm + 4096);
    float (*vs)[64] = (float(*)[64])(sm + 4096 + 4160);
    float (*ps)[64] = (float(*)[64])(sm + 4096 + 4160 + 4096);

    int b = blockIdx.z, h = blockIdx.y, st = blockIdx.x;
    int tid = threadIdx.x;
    int tx = tid & 15, ty = tid >> 4;

    const float* qbase = xq + (size_t)b * S_ * D_ + (size_t)h * S_ * HD_
                            + (size_t)st * 64 * HD_;
    for (int i = tid; i < 64 * 64; i += 256)
        qs[i >> 6][i & 63] = qbase[i];
    __syncthreads();

    if (tid < 64) {
        float m = 0.f;
        #pragma unroll 16
        for (int d = 0; d < 64; d++) m += qs[tid][d];
        m *= (1.f / 64.f);
        float v = 0.f;
        #pragma unroll 16
        for (int d = 0; d < 64; d++) { float t = qs[tid][d] - m; v += t * t; }
        float inv = rsqrtf(v * (1.f / 64.f) + EPS_);
        const float scale = 0.125f;
        #pragma unroll 16
        for (int d = 0; d < 64; d++)
            qs[tid][d] = ((qs[tid][d] - m) * inv * qnw[d] + qnb[d]) * scale;
    }
    __syncthreads();

    float o[4][4] = {};
    float mrow[4] = {-INFINITY, -INFINITY, -INFINITY, -INFINITY};
    float lrow[4] = {};

    const float* kb = g_kn + (size_t)b * N_ * HD_;
    const float* vb = xv   + (size_t)b * N_ * HD_;

    for (int n0 = 0; n0 < N_; n0 += 64) {
        for (int i = tid; i < 64 * 64; i += 256) {
            int r = i >> 6, d = i & 63;
            kt[d][r] = kb[(size_t)(n0 + r) * HD_ + d];
            vs[r][d] = vb[(size_t)(n0 + r) * HD_ + d];
        }
        __syncthreads();

        float sc[4][4] = {};
        #pragma unroll 8
        for (int d = 0; d < 64; d++) {
            float qv[4], kv[4];
            #pragma unroll
            for (int i = 0; i < 4; i++) qv[i] = qs[ty * 4 + i][d];
            #pragma unroll
            for (int j = 0; j < 4; j++) kv[j] = kt[d][tx * 4 + j];
            #pragma unroll
            for (int i = 0; i < 4; i++)
                #pragma unroll
                for (int j = 0; j < 4; j++) sc[i][j] += qv[i] * kv[j];
        }

        #pragma unroll
        for (int i = 0; i < 4; i++) {
            float mx = fmaxf(fmaxf(sc[i][0], sc[i][1]), fmaxf(sc[i][2], sc[i][3]));
            #pragma unroll
            for (int off = 8; off; off >>= 1)
                mx = fmaxf(mx, __shfl_xor_sync(0xffffffffu, mx, off, 16));
            float mnew  = fmaxf(mrow[i], mx);
            float alpha = __expf(mrow[i] - mnew);
            float psum = 0.f;
            #pragma unroll
            for (int j = 0; j < 4; j++) {
                float p = __expf(sc[i][j] - mnew);
                ps[ty * 4 + i][tx * 4 + j] = p;
                psum += p;
            }
            #pragma unroll
            for (int off = 8; off; off >>= 1)
                psum += __shfl_xor_sync(0xffffffffu, psum, off, 16);
            lrow[i] = lrow[i] * alpha + psum;
            mrow[i] = mnew;
            #pragma unroll
            for (int j = 0; j < 4; j++) o[i][j] *= alpha;
        }
        __syncthreads();

        #pragma unroll 8
        for (int k = 0; k < 64; k++) {
            float pv[4], vv[4];
            #pragma unroll
            for (int i = 0; i < 4; i++) pv[i] = ps[ty * 4 + i][k];
            #pragma unroll
            for (int j = 0; j < 4; j++) vv[j] = vs[k][tx * 4 + j];
            #pragma unroll
            for (int i = 0; i < 4; i++)
                #pragma unroll
                for (int j = 0; j < 4; j++) o[i][j] += pv[i] * vv[j];
        }
        __syncthreads();
    }

    float* xo = g_x + (size_t)b * S_ * D_ + (size_t)(st * 64) * D_ + (size_t)h * 64;
    #pragma unroll
    for (int i = 0; i < 4; i++) {
        float rinv = 1.f / lrow[i];
        #pragma unroll
        for (int j = 0; j < 4; j++)
            xo[(size_t)(ty * 4 + i) * D_ + tx * 4 + j] = o[i][j] * rinv;
    }
}

__global__ __launch_bounds__(256) void gemm_fb_kernel(
    const float* __restrict__ W, float* __restrict__ C)
{
    __shared__ float as[64][64];
    __shared__ float wt[64][65];
    int ct = blockIdx.x, rt = blockIdx.y;
    int tid = threadIdx.x, tx = tid & 15, ty = tid >> 4;
    float acc[4][4] = {};

    const float* Ab = g_xn + (size_t)rt * 64 * D_;
    const float* Wb = W    + (size_t)ct * 64 * D_;

    for (int k0 = 0; k0 < D_; k0 += 64) {
        for (int i = tid; i < 64 * 64; i += 256) {
            int r = i >> 6, k = i & 63;
            as[r][k] = Ab[(size_t)r * D_ + k0 + k];
            wt[k][r] = Wb[(size_t)r * D_ + k0 + k];
        }
        __syncthreads();
        #pragma unroll 8
        for (int k = 0; k < 64; k++) {
            float av[4], wv[4];
            #pragma unroll
            for (int i = 0; i < 4; i++) av[i] = as[ty * 4 + i][k];
            #pragma unroll
            for (int j = 0; j < 4; j++) wv[j] = wt[k][tx * 4 + j];
            #pragma unroll
            for (int i = 0; i < 4; i++)
                #pragma unroll
                for (int j = 0; j < 4; j++) acc[i][j] += av[i] * wv[j];
        }
        __syncthreads();
    }
    float* Cb = C + (size_t)(rt * 64) * D_ + ct * 64;
    #pragma unroll
    for (int i = 0; i < 4; i++)
        #pragma unroll
        for (int j = 0; j < 4; j++)
            Cb[(size_t)(ty * 4 + i) * D_ + tx * 4 + j] = acc[i][j];
}

// ---------------------------------------------------------------------------
extern "C" void kernel_launch(void* const* d_in, const int* in_sizes, int n_in,
                              void* d_out, int out_size)
{
    const float* x_q    = (const float*)d_in[0];
    const float* x_k    = (const float*)d_in[1];
    const float* x_v    = (const float*)d_in[2];
    const float* qn_w   = (const float*)d_in[3];
    const float* qn_b   = (const float*)d_in[4];
    const float* kn_w   = (const float*)d_in[5];
    const float* kn_b   = (const float*)d_in[6];
    const float* n_w    = (const float*)d_in[7];
    const float* n_b    = (const float*)d_in[8];
    const float* proj_w = (const float*)d_in[9];
    float* out = (float*)d_out;

    // Detect whether the loaded cubin contains the tcgen05 bodies.
    cudaFuncAttributes fa; fa.numRegs = 0;
    cudaFuncGetAttributes(&fa, attn_tc_kernel);
    bool fast = fa.numRegs >= 40;

    ln_k_kernel<<<(B_ * N_) / 8, 256>>>(x_k, kn_w, kn_b);

    if (fast) {
        cudaFuncSetAttribute(attn_tc_kernel,
                             cudaFuncAttributeMaxDynamicSharedMemorySize, ATTN_SMEM);
        cudaFuncSetAttribute(gemm_tc_kernel,
                             cudaFuncAttributeMaxDynamicSharedMemorySize, GEMM_SMEM);
        attn_tc_kernel<<<dim3(S_ / 128, H_, B_), 256, ATTN_SMEM>>>(x_q, x_v, qn_w, qn_b);
        ln_d_kernel<<<B_ * S_, 256>>>(n_w, n_b);
        gemm_tc_kernel<<<dim3(D_ / 128, (B_ * S_) / 128), 256, GEMM_SMEM>>>(proj_w, out);
    } else {
        cudaFuncSetAttribute(attn_fb_kernel,
                             cudaFuncAttributeMaxDynamicSharedMemorySize, ATTN_FB_SMEM);
        attn_fb_kernel<<<dim3(S_ / 64, H_, B_), 256, ATTN_FB_SMEM>>>(x_q, x_v, qn_w, qn_b);
        ln_d_kernel<<<B_ * S_, 256>>>(n_w, n_b);
        gemm_fb_kernel<<<dim3(D_ / 64, (B_ * S_) / 64), 256>>>(proj_w, out);
    }
}

// round 4
// speedup vs baseline: 6.5524x; 1.3891x over previous
#include <cuda_runtime.h>
#include <cstdint>
#include <math.h>

#define B_ 4
#define S_ 2048
#define N_ 2048
#define D_ 1024
#define H_ 16
#define HD_ 64
#define EPS_ 1e-5f

#ifndef __CUDA_ARCH__
  #define HAS_TC 1
#elif defined(__CUDA_ARCH_FEAT_SM103_ALL) || defined(__CUDA_ARCH_FEAT_SM100_ALL) || \
      defined(__CUDA_ARCH_FEAT_SM101_ALL)
  #define HAS_TC 1
#else
  #define HAS_TC 0
#endif

// Scratch
__device__ float g_kn[B_ * N_ * HD_];
__device__ float g_x[(size_t)B_ * S_ * D_];
__device__ float g_xn[(size_t)B_ * S_ * D_];   // fallback path only
__device__ float g_mu[B_ * S_];
__device__ float g_rs[B_ * S_];

// ---------------------------------------------------------------------------
// PTX helpers
// ---------------------------------------------------------------------------
__device__ __forceinline__ uint32_t smem_u32(const void* p) {
    uint32_t a;
    asm("{ .reg .u64 t; cvta.to.shared.u64 t, %1; cvt.u32.u64 %0, t; }"
        : "=r"(a) : "l"(p));
    return a;
}
__device__ __forceinline__ uint32_t elect1() {
    uint32_t r;
    asm volatile("{ .reg .pred p; elect.sync _|p, 0xFFFFFFFF; selp.b32 %0, 1, 0, p; }"
                 : "=r"(r));
    return r;
}
__device__ __forceinline__ float to_tf32(float x) {
    float r; asm("cvt.rna.tf32.f32 %0, %1;" : "=f"(r) : "f"(x)); return r;
}

#define SWZ(x) ((uint32_t)(x) ^ ((((uint32_t)(x)) >> 3) & 0x70u))

static constexpr uint64_t DESC_BASE_SW128 =
    (uint64_t(2) << 61) | (uint64_t(1) << 46) | (uint64_t(64) << 32) | (uint64_t(1) << 16);
#define MK_DESC(addr) (DESC_BASE_SW128 | ((uint64_t)((addr) >> 4) & 0x3FFFull))

// idesc: c=F32(1)@4, a=TF32(2)@7, b=TF32(2)@10, N/8@17, M/16@24
#define IDESC_TF32(Ncols) \
    ((1u << 4) | (2u << 7) | (2u << 10) | (((Ncols) / 8u) << 17) | (8u << 24))

#if HAS_TC
__device__ __forceinline__ void mma_tf32_ss(uint32_t d_tmem, uint64_t a_desc,
                                            uint64_t b_desc, uint32_t idesc, bool acc) {
    uint32_t en = acc ? 1u : 0u;
    asm volatile(
        "{\n\t.reg .pred p;\n\tsetp.ne.u32 p, %4, 0;\n\t"
        "tcgen05.mma.cta_group::1.kind::tf32 [%0], %1, %2, %3, {%5, %5, %5, %5}, p;\n\t}"
        :: "r"(d_tmem), "l"(a_desc), "l"(b_desc), "r"(idesc), "r"(en), "r"(0u)
        : "memory");
}
// TS mode: A operand in TMEM (1 tf32 per 32-bit column word, +8 cols per K=8 step)
__device__ __forceinline__ void mma_tf32_ts(uint32_t d_tmem, uint32_t a_tmem,
                                            uint64_t b_desc, uint32_t idesc, bool acc) {
    uint32_t en = acc ? 1u : 0u;
    asm volatile(
        "{\n\t.reg .pred p;\n\tsetp.ne.u32 p, %4, 0;\n\t"
        "tcgen05.mma.cta_group::1.kind::tf32 [%0], [%1], %2, %3, {%5, %5, %5, %5}, p;\n\t}"
        :: "r"(d_tmem), "r"(a_tmem), "l"(b_desc), "r"(idesc), "r"(en), "r"(0u)
        : "memory");
}

#define TC_ALLOC(slot, n) \
    asm volatile("tcgen05.alloc.cta_group::1.sync.aligned.shared::cta.b32 [%0], %1;" \
                 :: "r"(slot), "r"((uint32_t)(n)) : "memory")
#define TC_RELINQ() \
    asm volatile("tcgen05.relinquish_alloc_permit.cta_group::1.sync.aligned;")
#define TC_DEALLOC(tb, n) \
    asm volatile("tcgen05.dealloc.cta_group::1.sync.aligned.b32 %0, %1;" :: "r"(tb), "r"((uint32_t)(n)))
#define TC_COMMIT(mbar) \
    asm volatile("tcgen05.commit.cta_group::1.mbarrier::arrive::one.shared::cluster.b64 [%0];" \
                 :: "r"(mbar) : "memory")
#define TC_FENCE_BEFORE() asm volatile("tcgen05.fence::before_thread_sync;" ::: "memory")
#define TC_FENCE_AFTER()  asm volatile("tcgen05.fence::after_thread_sync;" ::: "memory")
#define TC_WAIT_LD()      asm volatile("tcgen05.wait::ld.sync.aligned;" ::: "memory")
#define TC_WAIT_ST()      asm volatile("tcgen05.wait::st.sync.aligned;" ::: "memory")
#define FENCE_ASYNC()     asm volatile("fence.proxy.async.shared::cta;" ::: "memory")

#define MBAR_INIT(a, c) \
    asm volatile("mbarrier.init.shared.b64 [%0], %1;" :: "r"(a), "r"((uint32_t)(c)) : "memory")
#define MBAR_WAIT(a, par) do { \
    uint32_t _m = (a); uint32_t _p = (par); uint32_t _d; \
    asm volatile("{\n\t.reg .pred p;\n\t" \
        "mbarrier.try_wait.parity.acquire.cta.shared::cta.b64 p, [%1], %2;\n\t" \
        "selp.b32 %0, 1, 0, p;\n\t}" : "=r"(_d) : "r"(_m), "r"(_p) : "memory"); \
    if (!_d) { \
        asm volatile("{\n\t.reg .pred P1;\n\tWL_%=:\n\t" \
            "mbarrier.try_wait.parity.acquire.cta.shared::cta.b64 P1, [%0], %1, 0x989680;\n\t" \
            "@P1 bra.uni WD_%=;\n\tbra.uni WL_%=;\n\tWD_%=:\n\t}" \
            :: "r"(_m), "r"(_p) : "memory"); \
    } } while (0)

#define LDTM_X32(r, a) \
    asm volatile("tcgen05.ld.sync.aligned.32x32b.x32.b32 " \
        "{%0,%1,%2,%3,%4,%5,%6,%7,%8,%9,%10,%11,%12,%13,%14,%15," \
        "%16,%17,%18,%19,%20,%21,%22,%23,%24,%25,%26,%27,%28,%29,%30,%31}, [%32];" \
        : "=r"((r)[0]), "=r"((r)[1]), "=r"((r)[2]), "=r"((r)[3]), \
          "=r"((r)[4]), "=r"((r)[5]), "=r"((r)[6]), "=r"((r)[7]), \
          "=r"((r)[8]), "=r"((r)[9]), "=r"((r)[10]), "=r"((r)[11]), \
          "=r"((r)[12]), "=r"((r)[13]), "=r"((r)[14]), "=r"((r)[15]), \
          "=r"((r)[16]), "=r"((r)[17]), "=r"((r)[18]), "=r"((r)[19]), \
          "=r"((r)[20]), "=r"((r)[21]), "=r"((r)[22]), "=r"((r)[23]), \
          "=r"((r)[24]), "=r"((r)[25]), "=r"((r)[26]), "=r"((r)[27]), \
          "=r"((r)[28]), "=r"((r)[29]), "=r"((r)[30]), "=r"((r)[31]) \
        : "r"(a))

#define STTM_X32(a, r) \
    asm volatile("tcgen05.st.sync.aligned.32x32b.x32.b32 [%0], " \
        "{%1,%2,%3,%4,%5,%6,%7,%8,%9,%10,%11,%12,%13,%14,%15,%16," \
        "%17,%18,%19,%20,%21,%22,%23,%24,%25,%26,%27,%28,%29,%30,%31,%32};" \
        :: "r"(a), \
           "r"((r)[0]), "r"((r)[1]), "r"((r)[2]), "r"((r)[3]), \
           "r"((r)[4]), "r"((r)[5]), "r"((r)[6]), "r"((r)[7]), \
           "r"((r)[8]), "r"((r)[9]), "r"((r)[10]), "r"((r)[11]), \
           "r"((r)[12]), "r"((r)[13]), "r"((r)[14]), "r"((r)[15]), \
           "r"((r)[16]), "r"((r)[17]), "r"((r)[18]), "r"((r)[19]), \
           "r"((r)[20]), "r"((r)[21]), "r"((r)[22]), "r"((r)[23]), \
           "r"((r)[24]), "r"((r)[25]), "r"((r)[26]), "r"((r)[27]), \
           "r"((r)[28]), "r"((r)[29]), "r"((r)[30]), "r"((r)[31]) \
        : "memory")
#endif  // HAS_TC

// ---------------------------------------------------------------------------
// Kernel 1: LayerNorm over K rows (HD=64). One warp per row.
// ---------------------------------------------------------------------------
__global__ __launch_bounds__(256) void ln_k_kernel(
    const float* __restrict__ xk, const float* __restrict__ w,
    const float* __restrict__ bb)
{
    int row  = blockIdx.x * 8 + (threadIdx.x >> 5);
    int lane = threadIdx.x & 31;
    const float* r = xk + (size_t)row * HD_;
    float a0 = r[lane], a1 = r[lane + 32];
    float s = a0 + a1;
    #pragma unroll
    for (int off = 16; off; off >>= 1) s += __shfl_xor_sync(0xffffffffu, s, off);
    float mean = s * (1.f / 64.f);
    float d0 = a0 - mean, d1 = a1 - mean;
    float vv = d0 * d0 + d1 * d1;
    #pragma unroll
    for (int off = 16; off; off >>= 1) vv += __shfl_xor_sync(0xffffffffu, vv, off);
    float inv = rsqrtf(vv * (1.f / 64.f) + EPS_);
    g_kn[(size_t)row * HD_ + lane]      = d0 * inv * w[lane]      + bb[lane];
    g_kn[(size_t)row * HD_ + lane + 32] = d1 * inv * w[lane + 32] + bb[lane + 32];
}

// ---------------------------------------------------------------------------
// Kernel 2 (fast): tcgen05 tf32 attention, TS-mode MMAs, P in TMEM.
// SMEM: K 32KB @AK (2 chunks [128n x 32d]); V 2x32KB @AV (4 chunks [64d x 32n]);
//       PART 1KB @APT. Total ~100KB -> 2 CTAs/SM.
// TMEM (256 cols): Q @0 (64), S/P @64 (128), O @192 (64).
// ---------------------------------------------------------------------------
#define AK 1024
#define AV 33792
#define APT 99328
#define ATTN_SMEM (APT + 1024 + 128)

__global__ __launch_bounds__(256, 2) void attn_tc_kernel(
    const float* __restrict__ xq, const float* __restrict__ xv,
    const float* __restrict__ qnw, const float* __restrict__ qnb)
{
#if HAS_TC
    extern __shared__ char smem[];
    uint32_t sb = smem_u32(smem);
    int tid = threadIdx.x, wid = tid >> 5, lane = tid & 31;
    int b = blockIdx.z, h = blockIdx.y, st = blockIdx.x;

    if (wid == 0) { TC_ALLOC(sb, 256); TC_RELINQ(); }
    if (tid == 0) MBAR_INIT(sb + 8, 1);
    __syncthreads();
    uint32_t tb;
    asm volatile("ld.shared.b32 %0, [%1];" : "=r"(tb) : "r"(sb));

    // ---- Q load + LN -> TMEM cols [0,64)  (warps 0..3; row = tid) ----
    if (tid < 128) {
        const float* qr = xq + (size_t)b * S_ * D_ + (size_t)h * S_ * HD_
                             + (size_t)(st * 128 + tid) * 64;
        float4 v[16];
        #pragma unroll
        for (int i = 0; i < 16; i++) v[i] = ((const float4*)qr)[i];
        float m = 0.f;
        #pragma unroll
        for (int i = 0; i < 16; i++) m += v[i].x + v[i].y + v[i].z + v[i].w;
        m *= (1.f / 64.f);
        float var = 0.f;
        #pragma unroll
        for (int i = 0; i < 16; i++) {
            float a = v[i].x - m, bq = v[i].y - m, c = v[i].z - m, d = v[i].w - m;
            var += a * a + bq * bq + c * c + d * d;
        }
        float inv = rsqrtf(var * (1.f / 64.f) + EPS_) * 0.125f;
        #pragma unroll
        for (int hc = 0; hc < 2; hc++) {
            uint32_t q[32];
            #pragma unroll
            for (int i = 0; i < 8; i++) {
                int iv = hc * 8 + i;
                float4 w4 = ((const float4*)qnw)[iv];
                float4 b4 = ((const float4*)qnb)[iv];
                q[i * 4 + 0] = __float_as_uint(to_tf32((v[iv].x - m) * inv * w4.x + b4.x * 0.125f));
                q[i * 4 + 1] = __float_as_uint(to_tf32((v[iv].y - m) * inv * w4.y + b4.y * 0.125f));
                q[i * 4 + 2] = __float_as_uint(to_tf32((v[iv].z - m) * inv * w4.z + b4.z * 0.125f));
                q[i * 4 + 3] = __float_as_uint(to_tf32((v[iv].w - m) * inv * w4.w + b4.w * 0.125f));
            }
            STTM_X32(tb + hc * 32, q);
        }
        TC_WAIT_ST();
    }

    const uint32_t idq  = IDESC_TF32(128);
    const uint32_t idpv = IDESC_TF32(64);
    const float* kball = g_kn + (size_t)b * N_ * HD_;
    const float* vball = xv   + (size_t)b * N_ * HD_;

    // ---- stage K(0), V(0)->buf0 ----
    {
        const float* kb = kball;
        const float* vb = vball;
        #pragma unroll
        for (int rep = 0; rep < 8; rep++) {
            int idx = tid + rep * 256;
            int nl = idx >> 4, d4 = idx & 15;
            float4 kv = ((const float4*)(kb + nl * 64))[d4];
            kv.x = to_tf32(kv.x); kv.y = to_tf32(kv.y);
            kv.z = to_tf32(kv.z); kv.w = to_tf32(kv.w);
            *(float4*)(smem + AK + (d4 >> 3) * 16384 + SWZ(nl * 128 + (d4 & 7) * 16)) = kv;
            float4 vv = ((const float4*)(vb + nl * 64))[d4];
            char* vtc = smem + AV + (nl >> 5) * 8192;
            int np = nl & 31;
            *(float*)(vtc + SWZ((d4 * 4 + 0) * 128 + np * 4)) = to_tf32(vv.x);
            *(float*)(vtc + SWZ((d4 * 4 + 1) * 128 + np * 4)) = to_tf32(vv.y);
            *(float*)(vtc + SWZ((d4 * 4 + 2) * 128 + np * 4)) = to_tf32(vv.z);
            *(float*)(vtc + SWZ((d4 * 4 + 3) * 128 + np * 4)) = to_tf32(vv.w);
        }
    }
    TC_FENCE_BEFORE();
    __syncthreads();
    if (wid == 0 && elect1()) {
        TC_FENCE_AFTER();
        FENCE_ASYNC();
        #pragma unroll
        for (int ks = 0; ks < 8; ks++) {
            uint64_t bd = MK_DESC(sb + AK + (ks >> 2) * 16384) + (ks & 3) * 2;
            mma_tf32_ts(tb + 64, tb + ks * 8, bd, idq, ks > 0);
        }
        TC_COMMIT(sb + 8);
    }

    int ph = 0;
    float lsum = 0.f;
    int half = wid >> 2;

    for (int it = 0; it < 16; it++) {
        MBAR_WAIT(sb + 8, ph); ph ^= 1;   // QK(it) done => PV(it-1) done too
        TC_FENCE_AFTER();

        // stage K(it+1), V(it+1) -> alt buffer (K free: QK(it) done; V alt free: PV(it-1) done)
        if (it < 15) {
            const float* kb = kball + (size_t)(it + 1) * 128 * 64;
            const float* vb = vball + (size_t)(it + 1) * 128 * 64;
            char* vbase = smem + AV + ((it + 1) & 1) * 32768;
            #pragma unroll
            for (int rep = 0; rep < 8; rep++) {
                int idx = tid + rep * 256;
                int nl = idx >> 4, d4 = idx & 15;
                float4 kv = ((const float4*)(kb + nl * 64))[d4];
                kv.x = to_tf32(kv.x); kv.y = to_tf32(kv.y);
                kv.z = to_tf32(kv.z); kv.w = to_tf32(kv.w);
                *(float4*)(smem + AK + (d4 >> 3) * 16384 + SWZ(nl * 128 + (d4 & 7) * 16)) = kv;
                float4 vv = ((const float4*)(vb + nl * 64))[d4];
                char* vtc = vbase + (nl >> 5) * 8192;
                int np = nl & 31;
                *(float*)(vtc + SWZ((d4 * 4 + 0) * 128 + np * 4)) = to_tf32(vv.x);
                *(float*)(vtc + SWZ((d4 * 4 + 1) * 128 + np * 4)) = to_tf32(vv.y);
                *(float*)(vtc + SWZ((d4 * 4 + 2) * 128 + np * 4)) = to_tf32(vv.z);
                *(float*)(vtc + SWZ((d4 * 4 + 3) * 128 + np * 4)) = to_tf32(vv.w);
            }
        }

        // softmax in TMEM: S -> exp -> P (in place)
        #pragma unroll
        for (int sbk = 0; sbk < 2; sbk++) {
            uint32_t r[32];
            uint32_t ta = tb + 64 + half * 64 + sbk * 32;
            LDTM_X32(r, ta);
            TC_WAIT_LD();
            #pragma unroll
            for (int j = 0; j < 32; j++) {
                float p = to_tf32(__expf(__uint_as_float(r[j])));
                lsum += p;
                r[j] = __float_as_uint(p);
            }
            STTM_X32(ta, r);
        }
        TC_WAIT_ST();
        TC_FENCE_BEFORE();
        __syncthreads();   // P in TMEM + staged K/V visible everywhere

        if (wid == 0 && elect1()) {
            TC_FENCE_AFTER();
            FENCE_ASYNC();
            // PV(it): O += P @ V  (in-order: runs before QK(it+1) below)
            char* vbase = smem + AV + (it & 1) * 32768;
            #pragma unroll
            for (int ks = 0; ks < 16; ks++) {
                uint64_t bd = MK_DESC(smem_u32(vbase) + (ks >> 2) * 8192) + (ks & 3) * 2;
                mma_tf32_ts(tb + 192, tb + 64 + ks * 8, bd, idpv, !(it == 0 && ks == 0));
            }
            if (it < 15) {
                #pragma unroll
                for (int ks = 0; ks < 8; ks++) {
                    uint64_t bd = MK_DESC(sb + AK + (ks >> 2) * 16384) + (ks & 3) * 2;
                    mma_tf32_ts(tb + 64, tb + ks * 8, bd, idq, ks > 0);
                }
            }
            TC_COMMIT(sb + 8);
        }
    }
    MBAR_WAIT(sb + 8, ph);
    TC_FENCE_AFTER();

    // combine row sums across halves
    *(float*)(smem + APT + (half * 128 + (wid & 3) * 32 + lane) * 4) = lsum;
    __syncthreads();

    if (tid < 128) {
        int row = wid * 32 + lane;
        uint32_t o0[32], o1[32];
        LDTM_X32(o0, tb + 192);
        LDTM_X32(o1, tb + 224);
        TC_WAIT_LD();
        float rin = 1.f / (*(float*)(smem + APT + row * 4)
                         + *(float*)(smem + APT + (128 + row) * 4));
        float* od = g_x + (size_t)b * S_ * D_ + (size_t)(st * 128 + row) * D_ + h * 64;
        #pragma unroll
        for (int j4 = 0; j4 < 8; j4++) {
            ((float4*)od)[j4] = make_float4(__uint_as_float(o0[j4 * 4 + 0]) * rin,
                                            __uint_as_float(o0[j4 * 4 + 1]) * rin,
                                            __uint_as_float(o0[j4 * 4 + 2]) * rin,
                                            __uint_as_float(o0[j4 * 4 + 3]) * rin);
            ((float4*)od)[8 + j4] = make_float4(__uint_as_float(o1[j4 * 4 + 0]) * rin,
                                                __uint_as_float(o1[j4 * 4 + 1]) * rin,
                                                __uint_as_float(o1[j4 * 4 + 2]) * rin,
                                                __uint_as_float(o1[j4 * 4 + 3]) * rin);
        }
    }
    TC_FENCE_BEFORE();
    __syncthreads();
    if (wid == 0) TC_DEALLOC(tb, 256);
#endif
}

// ---------------------------------------------------------------------------
// Kernel 3a (fast): row stats for LN over D (mean + rstd only)
// ---------------------------------------------------------------------------
__global__ __launch_bounds__(256) void ln_stats_kernel()
{
    __shared__ float red[8];
    int row = blockIdx.x;
    int tid = threadIdx.x;
    const float4* r4 = (const float4*)(g_x + (size_t)row * D_);
    float4 v = r4[tid];

    float s = v.x + v.y + v.z + v.w;
    #pragma unroll
    for (int off = 16; off; off >>= 1) s += __shfl_xor_sync(0xffffffffu, s, off);
    if ((tid & 31) == 0) red[tid >> 5] = s;
    __syncthreads();
    float tot = red[0] + red[1] + red[2] + red[3] + red[4] + red[5] + red[6] + red[7];
    float mean = tot * (1.f / D_);

    float dx = v.x - mean, dy = v.y - mean, dz = v.z - mean, dw = v.w - mean;
    float ss = dx * dx + dy * dy + dz * dz + dw * dw;
    __syncthreads();
    #pragma unroll
    for (int off = 16; off; off >>= 1) ss += __shfl_xor_sync(0xffffffffu, ss, off);
    if ((tid & 31) == 0) red[tid >> 5] = ss;
    __syncthreads();
    if (tid == 0) {
        float vtot = red[0] + red[1] + red[2] + red[3] + red[4] + red[5] + red[6] + red[7];
        g_mu[row] = mean;
        g_rs[row] = rsqrtf(vtot * (1.f / D_) + EPS_);
    }
}

// ---------------------------------------------------------------------------
// Kernel 3b (fallback): full LayerNorm over D, writes g_xn
// ---------------------------------------------------------------------------
__global__ __launch_bounds__(256) void ln_d_kernel(
    const float* __restrict__ w, const float* __restrict__ bb)
{
    __shared__ float red[8];
    int row = blockIdx.x;
    int tid = threadIdx.x;
    const float4* r4 = (const float4*)(g_x + (size_t)row * D_);
    float4 v = r4[tid];

    float s = v.x + v.y + v.z + v.w;
    #pragma unroll
    for (int off = 16; off; off >>= 1) s += __shfl_xor_sync(0xffffffffu, s, off);
    if ((tid & 31) == 0) red[tid >> 5] = s;
    __syncthreads();
    float tot = red[0] + red[1] + red[2] + red[3] + red[4] + red[5] + red[6] + red[7];
    float mean = tot * (1.f / D_);

    float dx = v.x - mean, dy = v.y - mean, dz = v.z - mean, dw = v.w - mean;
    float ss = dx * dx + dy * dy + dz * dz + dw * dw;
    __syncthreads();
    #pragma unroll
    for (int off = 16; off; off >>= 1) ss += __shfl_xor_sync(0xffffffffu, ss, off);
    if ((tid & 31) == 0) red[tid >> 5] = ss;
    __syncthreads();
    float vtot = red[0] + red[1] + red[2] + red[3] + red[4] + red[5] + red[6] + red[7];
    float inv = rsqrtf(vtot * (1.f / D_) + EPS_);

    float4 wv = ((const float4*)w)[tid];
    float4 bv = ((const float4*)bb)[tid];
    float4 o;
    o.x = dx * inv * wv.x + bv.x;
    o.y = dy * inv * wv.y + bv.y;
    o.z = dz * inv * wv.z + bv.z;
    o.w = dw * inv * wv.w + bv.w;
    ((float4*)(g_xn + (size_t)row * D_))[tid] = o;
}

// ---------------------------------------------------------------------------
// Kernel 4 (fast): tf32 tcgen05 GEMM with fused LN on A:
//   C = LN(g_x) @ W^T.  128x128 tiles, occ 2.
// ---------------------------------------------------------------------------
#define GA 1024
#define GB 33792
#define GEMM_SMEM (1024 + 65536 + 256)

__global__ __launch_bounds__(256, 2) void gemm_tc_kernel(
    const float* __restrict__ W, const float* __restrict__ nw,
    const float* __restrict__ nb, float* __restrict__ C)
{
#if HAS_TC
    extern __shared__ char smem[];
    uint32_t sb = smem_u32(smem);
    int tid = threadIdx.x, wid = tid >> 5, lane = tid & 31;
    int n0 = blockIdx.x * 128, m0 = blockIdx.y * 128;

    if (wid == 0) { TC_ALLOC(sb, 128); TC_RELINQ(); }
    if (tid == 0) { MBAR_INIT(sb + 8, 1); MBAR_INIT(sb + 16, 1); }
    __syncthreads();
    uint32_t tb;
    asm volatile("ld.shared.b32 %0, [%1];" : "=r"(tb) : "r"(sb));

    const uint32_t idc = IDESC_TF32(128);
    int ph0 = 0, ph1 = 0;

    for (int c = 0; c < 32; c++) {
        int bs = c & 1;
        if (c >= 2) {
            if (bs == 0) { MBAR_WAIT(sb + 8, ph0);  ph0 ^= 1; }
            else         { MBAR_WAIT(sb + 16, ph1); ph1 ^= 1; }
        }
        int k0 = c * 32;
        char* abuf = smem + GA + bs * 16384;
        char* bbuf = smem + GB + bs * 16384;
        #pragma unroll
        for (int rep = 0; rep < 4; rep++) {
            int idx = tid + rep * 256;
            int r = idx >> 3, k4 = idx & 7;
            float mu = g_mu[m0 + r], rs = g_rs[m0 + r];
            float4 a4 = *(const float4*)(g_x + (size_t)(m0 + r) * D_ + k0 + k4 * 4);
            float4 w4 = *(const float4*)(nw + k0 + k4 * 4);
            float4 c4 = *(const float4*)(nb + k0 + k4 * 4);
            a4.x = to_tf32((a4.x - mu) * rs * w4.x + c4.x);
            a4.y = to_tf32((a4.y - mu) * rs * w4.y + c4.y);
            a4.z = to_tf32((a4.z - mu) * rs * w4.z + c4.z);
            a4.w = to_tf32((a4.w - mu) * rs * w4.w + c4.w);
            *(float4*)(abuf + SWZ(r * 128 + k4 * 16)) = a4;
            float4 b4 = *(const float4*)(W + (size_t)(n0 + r) * D_ + k0 + k4 * 4);
            b4.x = to_tf32(b4.x); b4.y = to_tf32(b4.y);
            b4.z = to_tf32(b4.z); b4.w = to_tf32(b4.w);
            *(float4*)(bbuf + SWZ(r * 128 + k4 * 16)) = b4;
        }
        __syncthreads();
        if (wid == 0 && elect1()) {
            FENCE_ASYNC();
            uint64_t ad = MK_DESC(sb + GA + bs * 16384);
            uint64_t bd = MK_DESC(sb + GB + bs * 16384);
            #pragma unroll
            for (int ks = 0; ks < 4; ks++)
                mma_tf32_ss(tb, ad + ks * 2, bd + ks * 2, idc, !(c == 0 && ks == 0));
            TC_COMMIT(sb + 8 + bs * 8);
        }
    }
    MBAR_WAIT(sb + 8, ph0);
    MBAR_WAIT(sb + 16, ph1);
    TC_FENCE_AFTER();

    int half = wid >> 2;
    int row = (wid & 3) * 32 + lane;
    uint32_t o0[32], o1[32];
    LDTM_X32(o0, tb + half * 64);
    LDTM_X32(o1, tb + half * 64 + 32);
    TC_WAIT_LD();
    float* cd = C + (size_t)(m0 + row) * D_ + n0 + half * 64;
    #pragma unroll
    for (int j4 = 0; j4 < 8; j4++) {
        ((float4*)cd)[j4] = make_float4(__uint_as_float(o0[j4 * 4 + 0]),
                                        __uint_as_float(o0[j4 * 4 + 1]),
                                        __uint_as_float(o0[j4 * 4 + 2]),
                                        __uint_as_float(o0[j4 * 4 + 3]));
        ((float4*)cd)[8 + j4] = make_float4(__uint_as_float(o1[j4 * 4 + 0]),
                                            __uint_as_float(o1[j4 * 4 + 1]),
                                            __uint_as_float(o1[j4 * 4 + 2]),
                                            __uint_as_float(o1[j4 * 4 + 3]));
    }
    TC_FENCE_BEFORE();
    __syncthreads();
    if (wid == 0) TC_DEALLOC(tb, 128);
#endif
}

// ---------------------------------------------------------------------------
// Fallback kernels (round-1, proven correct)
// ---------------------------------------------------------------------------
#define ATTN_FB_SMEM ((4096 + 4160 + 4096 + 4096) * 4)

__global__ __launch_bounds__(256, 1) void attn_fb_kernel(
    const float* __restrict__ xq, const float* __restrict__ xv,
    const float* __restrict__ qnw, const float* __restrict__ qnb)
{
    extern __shared__ float sm[];
    float (*qs)[64] = (float(*)[64])(sm);
    float (*kt)[65] = (float(*)[65])(sm + 4096);
    float (*vs)[64] = (float(*)[64])(sm + 4096 + 4160);
    float (*ps)[64] = (float(*)[64])(sm + 4096 + 4160 + 4096);

    int b = blockIdx.z, h = blockIdx.y, st = blockIdx.x;
    int tid = threadIdx.x;
    int tx = tid & 15, ty = tid >> 4;

    const float* qbase = xq + (size_t)b * S_ * D_ + (size_t)h * S_ * HD_
                            + (size_t)st * 64 * HD_;
    for (int i = tid; i < 64 * 64; i += 256)
        qs[i >> 6][i & 63] = qbase[i];
    __syncthreads();

    if (tid < 64) {
        float m = 0.f;
        #pragma unroll 16
        for (int d = 0; d < 64; d++) m += qs[tid][d];
        m *= (1.f / 64.f);
        float v = 0.f;
        #pragma unroll 16
        for (int d = 0; d < 64; d++) { float t = qs[tid][d] - m; v += t * t; }
        float inv = rsqrtf(v * (1.f / 64.f) + EPS_);
        const float scale = 0.125f;
        #pragma unroll 16
        for (int d = 0; d < 64; d++)
            qs[tid][d] = ((qs[tid][d] - m) * inv * qnw[d] + qnb[d]) * scale;
    }
    __syncthreads();

    float o[4][4] = {};
    float mrow[4] = {-INFINITY, -INFINITY, -INFINITY, -INFINITY};
    float lrow[4] = {};

    const float* kb = g_kn + (size_t)b * N_ * HD_;
    const float* vb = xv   + (size_t)b * N_ * HD_;

    for (int n0 = 0; n0 < N_; n0 += 64) {
        for (int i = tid; i < 64 * 64; i += 256) {
            int r = i >> 6, d = i & 63;
            kt[d][r] = kb[(size_t)(n0 + r) * HD_ + d];
            vs[r][d] = vb[(size_t)(n0 + r) * HD_ + d];
        }
        __syncthreads();

        float sc[4][4] = {};
        #pragma unroll 8
        for (int d = 0; d < 64; d++) {
            float qv[4], kv[4];
            #pragma unroll
            for (int i = 0; i < 4; i++) qv[i] = qs[ty * 4 + i][d];
            #pragma unroll
            for (int j = 0; j < 4; j++) kv[j] = kt[d][tx * 4 + j];
            #pragma unroll
            for (int i = 0; i < 4; i++)
                #pragma unroll
                for (int j = 0; j < 4; j++) sc[i][j] += qv[i] * kv[j];
        }

        #pragma unroll
        for (int i = 0; i < 4; i++) {
            float mx = fmaxf(fmaxf(sc[i][0], sc[i][1]), fmaxf(sc[i][2], sc[i][3]));
            #pragma unroll
            for (int off = 8; off; off >>= 1)
                mx = fmaxf(mx, __shfl_xor_sync(0xffffffffu, mx, off, 16));
            float mnew  = fmaxf(mrow[i], mx);
            float alpha = __expf(mrow[i] - mnew);
            float psum = 0.f;
            #pragma unroll
            for (int j = 0; j < 4; j++) {
                float p = __expf(sc[i][j] - mnew);
                ps[ty * 4 + i][tx * 4 + j] = p;
                psum += p;
            }
            #pragma unroll
            for (int off = 8; off; off >>= 1)
                psum += __shfl_xor_sync(0xffffffffu, psum, off, 16);
            lrow[i] = lrow[i] * alpha + psum;
            mrow[i] = mnew;
            #pragma unroll
            for (int j = 0; j < 4; j++) o[i][j] *= alpha;
        }
        __syncthreads();

        #pragma unroll 8
        for (int k = 0; k < 64; k++) {
            float pv[4], vv[4];
            #pragma unroll
            for (int i = 0; i < 4; i++) pv[i] = ps[ty * 4 + i][k];
            #pragma unroll
            for (int j = 0; j < 4; j++) vv[j] = vs[k][tx * 4 + j];
            #pragma unroll
            for (int i = 0; i < 4; i++)
                #pragma unroll
                for (int j = 0; j < 4; j++) o[i][j] += pv[i] * vv[j];
        }
        __syncthreads();
    }

    float* xo = g_x + (size_t)b * S_ * D_ + (size_t)(st * 64) * D_ + (size_t)h * 64;
    #pragma unroll
    for (int i = 0; i < 4; i++) {
        float rinv = 1.f / lrow[i];
        #pragma unroll
        for (int j = 0; j < 4; j++)
            xo[(size_t)(ty * 4 + i) * D_ + tx * 4 + j] = o[i][j] * rinv;
    }
}

__global__ __launch_bounds__(256) void gemm_fb_kernel(
    const float* __restrict__ W, float* __restrict__ C)
{
    __shared__ float as[64][64];
    __shared__ float wt[64][65];
    int ct = blockIdx.x, rt = blockIdx.y;
    int tid = threadIdx.x, tx = tid & 15, ty = tid >> 4;
    float acc[4][4] = {};

    const float* Ab = g_xn + (size_t)rt * 64 * D_;
    const float* Wb = W    + (size_t)ct * 64 * D_;

    for (int k0 = 0; k0 < D_; k0 += 64) {
        for (int i = tid; i < 64 * 64; i += 256) {
            int r = i >> 6, k = i & 63;
            as[r][k] = Ab[(size_t)r * D_ + k0 + k];
            wt[k][r] = Wb[(size_t)r * D_ + k0 + k];
        }
        __syncthreads();
        #pragma unroll 8
        for (int k = 0; k < 64; k++) {
            float av[4], wv[4];
            #pragma unroll
            for (int i = 0; i < 4; i++) av[i] = as[ty * 4 + i][k];
            #pragma unroll
            for (int j = 0; j < 4; j++) wv[j] = wt[k][tx * 4 + j];
            #pragma unroll
            for (int i = 0; i < 4; i++)
                #pragma unroll
                for (int j = 0; j < 4; j++) acc[i][j] += av[i] * wv[j];
        }
        __syncthreads();
    }
    float* Cb = C + (size_t)(rt * 64) * D_ + ct * 64;
    #pragma unroll
    for (int i = 0; i < 4; i++)
        #pragma unroll
        for (int j = 0; j < 4; j++)
            Cb[(size_t)(ty * 4 + i) * D_ + tx * 4 + j] = acc[i][j];
}

// ---------------------------------------------------------------------------
extern "C" void kernel_launch(void* const* d_in, const int* in_sizes, int n_in,
                              void* d_out, int out_size)
{
    const float* x_q    = (const float*)d_in[0];
    const float* x_k    = (const float*)d_in[1];
    const float* x_v    = (const float*)d_in[2];
    const float* qn_w   = (const float*)d_in[3];
    const float* qn_b   = (const float*)d_in[4];
    const float* kn_w   = (const float*)d_in[5];
    const float* kn_b   = (const float*)d_in[6];
    const float* n_w    = (const float*)d_in[7];
    const float* n_b    = (const float*)d_in[8];
    const float* proj_w = (const float*)d_in[9];
    float* out = (float*)d_out;

    cudaFuncAttributes fa; fa.numRegs = 0;
    cudaFuncGetAttributes(&fa, attn_tc_kernel);
    bool fast = fa.numRegs >= 40;

    ln_k_kernel<<<(B_ * N_) / 8, 256>>>(x_k, kn_w, kn_b);

    if (fast) {
        cudaFuncSetAttribute(attn_tc_kernel,
                             cudaFuncAttributeMaxDynamicSharedMemorySize, ATTN_SMEM);
        cudaFuncSetAttribute(gemm_tc_kernel,
                             cudaFuncAttributeMaxDynamicSharedMemorySize, GEMM_SMEM);
        attn_tc_kernel<<<dim3(S_ / 128, H_, B_), 256, ATTN_SMEM>>>(x_q, x_v, qn_w, qn_b);
        ln_stats_kernel<<<B_ * S_, 256>>>();
        gemm_tc_kernel<<<dim3(D_ / 128, (B_ * S_) / 128), 256, GEMM_SMEM>>>(
            proj_w, n_w, n_b, out);
    } else {
        cudaFuncSetAttribute(attn_fb_kernel,
                             cudaFuncAttributeMaxDynamicSharedMemorySize, ATTN_FB_SMEM);
        attn_fb_kernel<<<dim3(S_ / 64, H_, B_), 256, ATTN_FB_SMEM>>>(x_q, x_v, qn_w, qn_b);
        ln_d_kernel<<<B_ * S_, 256>>>(n_w, n_b);
        gemm_fb_kernel<<<dim3(D_ / 64, (B_ * S_) / 64), 256>>>(proj_w, out);
    }
}

// round 5
// speedup vs baseline: 11.3999x; 1.7398x over previous
#include <cuda_runtime.h>
#include <cuda_fp16.h>
#include <cstdint>
#include <math.h>

#define B_ 4
#define S_ 2048
#define N_ 2048
#define D_ 1024
#define H_ 16
#define HD_ 64
#define EPS_ 1e-5f

#ifndef __CUDA_ARCH__
  #define HAS_TC 1
#elif defined(__CUDA_ARCH_FEAT_SM103_ALL) || defined(__CUDA_ARCH_FEAT_SM100_ALL) || \
      defined(__CUDA_ARCH_FEAT_SM101_ALL)
  #define HAS_TC 1
#else
  #define HAS_TC 0
#endif

// Scratch
__device__ __half g_kn[B_ * N_ * HD_];                 // normalized K, fp16
__device__ __half g_vt[B_ * HD_ * N_];                 // V transposed [b][d][n], fp16
__device__ __half g_wh[D_ * D_];                       // proj_w fp16
__device__ float  g_x [(size_t)B_ * S_ * D_];          // attention out (B,S,D) fp32
__device__ __half g_xh[(size_t)B_ * S_ * D_];          // LN(x) fp16
__device__ float  g_xn[(size_t)B_ * S_ * D_];          // fallback only

// ---------------------------------------------------------------------------
// helpers
// ---------------------------------------------------------------------------
__device__ __forceinline__ uint32_t smem_u32(const void* p) {
    uint32_t a;
    asm("{ .reg .u64 t; cvta.to.shared.u64 t, %1; cvt.u32.u64 %0, t; }"
        : "=r"(a) : "l"(p));
    return a;
}
__device__ __forceinline__ uint32_t elect1() {
    uint32_t r;
    asm volatile("{ .reg .pred p; elect.sync _|p, 0xFFFFFFFF; selp.b32 %0, 1, 0, p; }"
                 : "=r"(r));
    return r;
}
__device__ __forceinline__ uint32_t pack2h(float a, float b) {
    __half2 h = __floats2half2_rn(a, b);
    return *reinterpret_cast<uint32_t*>(&h);
}

#define SWZ(x) ((uint32_t)(x) ^ ((((uint32_t)(x)) >> 3) & 0x70u))

static constexpr uint64_t DESC_BASE_SW128 =
    (uint64_t(2) << 61) | (uint64_t(1) << 46) | (uint64_t(64) << 32) | (uint64_t(1) << 16);
#define MK_DESC(addr) (DESC_BASE_SW128 | ((uint64_t)((addr) >> 4) & 0x3FFFull))

// idesc kind::f16 (fp16 in, fp32 accum): dtype F32=1 @4, a/b FP16=0 @7/@10,
// N/8 @17, M=128 -> 8 @24   (decoded from verified bf16 constant 0x8080490)
#define IDESC_F16(Ncols) ((1u << 4) | (((Ncols) / 8u) << 17) | (8u << 24))

#if HAS_TC
__device__ __forceinline__ void mma_f16_ss(uint32_t d_tmem, uint64_t a_desc,
                                           uint64_t b_desc, uint32_t idesc, bool acc) {
    uint32_t en = acc ? 1u : 0u;
    asm volatile(
        "{\n\t.reg .pred p;\n\tsetp.ne.u32 p, %4, 0;\n\t"
        "tcgen05.mma.cta_group::1.kind::f16 [%0], %1, %2, %3, {%5, %5, %5, %5}, p;\n\t}"
        :: "r"(d_tmem), "l"(a_desc), "l"(b_desc), "r"(idesc), "r"(en), "r"(0u)
        : "memory");
}
__device__ __forceinline__ void mma_f16_ts(uint32_t d_tmem, uint32_t a_tmem,
                                           uint64_t b_desc, uint32_t idesc, bool acc) {
    uint32_t en = acc ? 1u : 0u;
    asm volatile(
        "{\n\t.reg .pred p;\n\tsetp.ne.u32 p, %4, 0;\n\t"
        "tcgen05.mma.cta_group::1.kind::f16 [%0], [%1], %2, %3, {%5, %5, %5, %5}, p;\n\t}"
        :: "r"(d_tmem), "r"(a_tmem), "l"(b_desc), "r"(idesc), "r"(en), "r"(0u)
        : "memory");
}

#define TC_ALLOC(slot, n) \
    asm volatile("tcgen05.alloc.cta_group::1.sync.aligned.shared::cta.b32 [%0], %1;" \
                 :: "r"(slot), "r"((uint32_t)(n)) : "memory")
#define TC_RELINQ() \
    asm volatile("tcgen05.relinquish_alloc_permit.cta_group::1.sync.aligned;")
#define TC_DEALLOC(tb, n) \
    asm volatile("tcgen05.dealloc.cta_group::1.sync.aligned.b32 %0, %1;" :: "r"(tb), "r"((uint32_t)(n)))
#define TC_COMMIT(mbar) \
    asm volatile("tcgen05.commit.cta_group::1.mbarrier::arrive::one.shared::cluster.b64 [%0];" \
                 :: "r"(mbar) : "memory")
#define TC_FENCE_BEFORE() asm volatile("tcgen05.fence::before_thread_sync;" ::: "memory")
#define TC_FENCE_AFTER()  asm volatile("tcgen05.fence::after_thread_sync;" ::: "memory")
#define TC_WAIT_LD()      asm volatile("tcgen05.wait::ld.sync.aligned;" ::: "memory")
#define TC_WAIT_ST()      asm volatile("tcgen05.wait::st.sync.aligned;" ::: "memory")
#define FENCE_ASYNC()     asm volatile("fence.proxy.async.shared::cta;" ::: "memory")

#define MBAR_INIT(a, c) \
    asm volatile("mbarrier.init.shared.b64 [%0], %1;" :: "r"(a), "r"((uint32_t)(c)) : "memory")
#define MBAR_WAIT(a, par) do { \
    uint32_t _m = (a); uint32_t _p = (par); uint32_t _d; \
    asm volatile("{\n\t.reg .pred p;\n\t" \
        "mbarrier.try_wait.parity.acquire.cta.shared::cta.b64 p, [%1], %2;\n\t" \
        "selp.b32 %0, 1, 0, p;\n\t}" : "=r"(_d) : "r"(_m), "r"(_p) : "memory"); \
    if (!_d) { \
        asm volatile("{\n\t.reg .pred P1;\n\tWL_%=:\n\t" \
            "mbarrier.try_wait.parity.acquire.cta.shared::cta.b64 P1, [%0], %1, 0x989680;\n\t" \
            "@P1 bra.uni WD_%=;\n\tbra.uni WL_%=;\n\tWD_%=:\n\t}" \
            :: "r"(_m), "r"(_p) : "memory"); \
    } } while (0)

#define LDTM_X32(r, a) \
    asm volatile("tcgen05.ld.sync.aligned.32x32b.x32.b32 " \
        "{%0,%1,%2,%3,%4,%5,%6,%7,%8,%9,%10,%11,%12,%13,%14,%15," \
        "%16,%17,%18,%19,%20,%21,%22,%23,%24,%25,%26,%27,%28,%29,%30,%31}, [%32];" \
        : "=r"((r)[0]), "=r"((r)[1]), "=r"((r)[2]), "=r"((r)[3]), \
          "=r"((r)[4]), "=r"((r)[5]), "=r"((r)[6]), "=r"((r)[7]), \
          "=r"((r)[8]), "=r"((r)[9]), "=r"((r)[10]), "=r"((r)[11]), \
          "=r"((r)[12]), "=r"((r)[13]), "=r"((r)[14]), "=r"((r)[15]), \
          "=r"((r)[16]), "=r"((r)[17]), "=r"((r)[18]), "=r"((r)[19]), \
          "=r"((r)[20]), "=r"((r)[21]), "=r"((r)[22]), "=r"((r)[23]), \
          "=r"((r)[24]), "=r"((r)[25]), "=r"((r)[26]), "=r"((r)[27]), \
          "=r"((r)[28]), "=r"((r)[29]), "=r"((r)[30]), "=r"((r)[31]) \
        : "r"(a))

#define STTM_X32(a, r) \
    asm volatile("tcgen05.st.sync.aligned.32x32b.x32.b32 [%0], " \
        "{%1,%2,%3,%4,%5,%6,%7,%8,%9,%10,%11,%12,%13,%14,%15,%16," \
        "%17,%18,%19,%20,%21,%22,%23,%24,%25,%26,%27,%28,%29,%30,%31,%32};" \
        :: "r"(a), \
           "r"((r)[0]), "r"((r)[1]), "r"((r)[2]), "r"((r)[3]), \
           "r"((r)[4]), "r"((r)[5]), "r"((r)[6]), "r"((r)[7]), \
           "r"((r)[8]), "r"((r)[9]), "r"((r)[10]), "r"((r)[11]), \
           "r"((r)[12]), "r"((r)[13]), "r"((r)[14]), "r"((r)[15]), \
           "r"((r)[16]), "r"((r)[17]), "r"((r)[18]), "r"((r)[19]), \
           "r"((r)[20]), "r"((r)[21]), "r"((r)[22]), "r"((r)[23]), \
           "r"((r)[24]), "r"((r)[25]), "r"((r)[26]), "r"((r)[27]), \
           "r"((r)[28]), "r"((r)[29]), "r"((r)[30]), "r"((r)[31]) \
        : "memory")
#endif  // HAS_TC

// ---------------------------------------------------------------------------
// Kernel 1: LayerNorm over K rows -> fp16 g_kn. One warp per row.
// ---------------------------------------------------------------------------
__global__ __launch_bounds__(256) void ln_k_kernel(
    const float* __restrict__ xk, const float* __restrict__ w,
    const float* __restrict__ bb)
{
    int row  = blockIdx.x * 8 + (threadIdx.x >> 5);
    int lane = threadIdx.x & 31;
    const float* r = xk + (size_t)row * HD_;
    float a0 = r[lane], a1 = r[lane + 32];
    float s = a0 + a1;
    #pragma unroll
    for (int off = 16; off; off >>= 1) s += __shfl_xor_sync(0xffffffffu, s, off);
    float mean = s * (1.f / 64.f);
    float d0 = a0 - mean, d1 = a1 - mean;
    float vv = d0 * d0 + d1 * d1;
    #pragma unroll
    for (int off = 16; off; off >>= 1) vv += __shfl_xor_sync(0xffffffffu, vv, off);
    float inv = rsqrtf(vv * (1.f / 64.f) + EPS_);
    g_kn[(size_t)row * HD_ + lane]      = __float2half_rn(d0 * inv * w[lane]      + bb[lane]);
    g_kn[(size_t)row * HD_ + lane + 32] = __float2half_rn(d1 * inv * w[lane + 32] + bb[lane + 32]);
}

// ---------------------------------------------------------------------------
// Kernel 1b: V transpose + fp16: g_vt[b][d][n] = fp16(x_v[b][n][d])
// ---------------------------------------------------------------------------
__global__ __launch_bounds__(256) void cvt_v_kernel(const float* __restrict__ xv)
{
    __shared__ float t[64][65];
    int b = blockIdx.y, n0 = blockIdx.x * 64;
    int tid = threadIdx.x;
    #pragma unroll
    for (int rep = 0; rep < 4; rep++) {
        int idx = tid + rep * 256;          // 0..1023
        int n = idx >> 4, j = idx & 15;
        float4 v = ((const float4*)(xv + (size_t)b * N_ * HD_ + (size_t)(n0 + n) * HD_))[j];
        t[n][j * 4 + 0] = v.x; t[n][j * 4 + 1] = v.y;
        t[n][j * 4 + 2] = v.z; t[n][j * 4 + 3] = v.w;
    }
    __syncthreads();
    int d = tid >> 2, g = tid & 3;          // d 0..63, 16-n group
    uint32_t wds[8];
    #pragma unroll
    for (int m = 0; m < 8; m++)
        wds[m] = pack2h(t[g * 16 + 2 * m][d], t[g * 16 + 2 * m + 1][d]);
    __half* dst = g_vt + (size_t)b * HD_ * N_ + (size_t)d * N_ + n0 + g * 16;
    ((uint4*)dst)[0] = make_uint4(wds[0], wds[1], wds[2], wds[3]);
    ((uint4*)dst)[1] = make_uint4(wds[4], wds[5], wds[6], wds[7]);
}

// ---------------------------------------------------------------------------
// Kernel 1c: proj_w -> fp16
// ---------------------------------------------------------------------------
__global__ __launch_bounds__(256) void cvt_w_kernel(const float* __restrict__ W)
{
    int idx = blockIdx.x * 256 + threadIdx.x;   // one uint4 (8 halves) each
    const float4* src = (const float4*)(W) + idx * 2;
    float4 a = src[0], bq = src[1];
    ((uint4*)g_wh)[idx] = make_uint4(pack2h(a.x, a.y), pack2h(a.z, a.w),
                                     pack2h(bq.x, bq.y), pack2h(bq.z, bq.w));
}

// ---------------------------------------------------------------------------
// Kernel 2 (fast): tcgen05 fp16 attention.
// SMEM: Q @1024 (16KB), K @17408 (16KB), V 2x16KB @33792, partials @66560.
// TMEM (256): S fp32 @0 (128), P fp16 @128 (64), O fp32 @192 (64).
// ---------------------------------------------------------------------------
#define AQ 1024
#define AK 17408
#define AV 33792
#define APT 66560
#define ATTN_SMEM (APT + 1024 + 128)

__global__ __launch_bounds__(256, 2) void attn_tc_kernel(
    const float* __restrict__ xq,
    const float* __restrict__ qnw, const float* __restrict__ qnb)
{
#if HAS_TC
    extern __shared__ char smem[];
    uint32_t sb = smem_u32(smem);
    int tid = threadIdx.x, wid = tid >> 5, lane = tid & 31;
    int b = blockIdx.z, h = blockIdx.y, st = blockIdx.x;

    if (wid == 0) { TC_ALLOC(sb, 256); TC_RELINQ(); }
    if (tid == 0) MBAR_INIT(sb + 8, 1);
    __syncthreads();
    uint32_t tb;
    asm volatile("ld.shared.b32 %0, [%1];" : "=r"(tb) : "r"(sb));

    // ---- Q load + LN -> fp16 SMEM tile [128 x 64] ----
    if (tid < 128) {
        const float* qr = xq + (size_t)b * S_ * D_ + (size_t)h * S_ * HD_
                             + (size_t)(st * 128 + tid) * 64;
        float4 v[16];
        #pragma unroll
        for (int i = 0; i < 16; i++) v[i] = ((const float4*)qr)[i];
        float m = 0.f;
        #pragma unroll
        for (int i = 0; i < 16; i++) m += v[i].x + v[i].y + v[i].z + v[i].w;
        m *= (1.f / 64.f);
        float var = 0.f;
        #pragma unroll
        for (int i = 0; i < 16; i++) {
            float a = v[i].x - m, bq = v[i].y - m, c = v[i].z - m, d = v[i].w - m;
            var += a * a + bq * bq + c * c + d * d;
        }
        float inv = rsqrtf(var * (1.f / 64.f) + EPS_) * 0.125f;
        uint32_t q[32];
        #pragma unroll
        for (int i = 0; i < 16; i++) {
            float4 w4 = ((const float4*)qnw)[i];
            float4 b4 = ((const float4*)qnb)[i];
            float x0 = (v[i].x - m) * inv * w4.x + b4.x * 0.125f;
            float x1 = (v[i].y - m) * inv * w4.y + b4.y * 0.125f;
            float x2 = (v[i].z - m) * inv * w4.z + b4.z * 0.125f;
            float x3 = (v[i].w - m) * inv * w4.w + b4.w * 0.125f;
            q[2 * i]     = pack2h(x0, x1);
            q[2 * i + 1] = pack2h(x2, x3);
        }
        #pragma unroll
        for (int j = 0; j < 8; j++)
            *(uint4*)(smem + AQ + SWZ(tid * 128 + j * 16)) =
                make_uint4(q[4 * j], q[4 * j + 1], q[4 * j + 2], q[4 * j + 3]);
    }

    const uint32_t idq  = IDESC_F16(128);
    const uint32_t idpv = IDESC_F16(64);
    const __half* kball = g_kn + (size_t)b * N_ * HD_;
    const __half* vtall = g_vt + (size_t)b * HD_ * N_;

    // ---- stage K(0), V(0) ----
    #pragma unroll
    for (int rep = 0; rep < 4; rep++) {
        int idx = tid + rep * 256;          // 0..1023
        int nl = idx >> 3, j = idx & 7;
        uint4 kv = ((const uint4*)(kball + (size_t)nl * 64))[j];
        *(uint4*)(smem + AK + SWZ(nl * 128 + j * 16)) = kv;
        int d = idx >> 4, jj = idx & 15;    // V^T tile [64 d x 128 n], blocked atoms
        uint4 vv = *(const uint4*)(vtall + (size_t)d * N_ + jj * 8);
        uint32_t off = ((d >> 3) + (jj >> 3) * 8) * 1024 + (d & 7) * 128 + (jj & 7) * 16;
        *(uint4*)(smem + AV + SWZ(off)) = vv;
    }
    TC_FENCE_BEFORE();
    __syncthreads();
    if (wid == 0 && elect1()) {
        TC_FENCE_AFTER();
        FENCE_ASYNC();
        uint64_t ad = MK_DESC(sb + AQ), bd = MK_DESC(sb + AK);
        #pragma unroll
        for (int ks = 0; ks < 4; ks++)
            mma_f16_ss(tb, ad + ks * 2, bd + ks * 2, idq, ks > 0);
        TC_COMMIT(sb + 8);
    }

    int ph = 0;
    float lsum = 0.f;
    int half = wid >> 2;
    int row = (wid & 3) * 32 + lane;

    for (int it = 0; it < 16; it++) {
        MBAR_WAIT(sb + 8, ph); ph ^= 1;     // QK(it) done (and PV(it-1))
        TC_FENCE_AFTER();

        // exp: S fp32 -> P fp16 (packed pairs)
        uint32_t r0[32], r1[32];
        LDTM_X32(r0, tb + half * 64);
        LDTM_X32(r1, tb + half * 64 + 32);
        TC_WAIT_LD();
        uint32_t pk[32];
        #pragma unroll
        for (int j = 0; j < 16; j++) {
            float e0 = __expf(__uint_as_float(r0[2 * j]));
            float e1 = __expf(__uint_as_float(r0[2 * j + 1]));
            lsum += e0 + e1;
            pk[j] = pack2h(e0, e1);
        }
        #pragma unroll
        for (int j = 0; j < 16; j++) {
            float e0 = __expf(__uint_as_float(r1[2 * j]));
            float e1 = __expf(__uint_as_float(r1[2 * j + 1]));
            lsum += e0 + e1;
            pk[16 + j] = pack2h(e0, e1);
        }
        STTM_X32(tb + 128 + half * 32, pk);
        TC_WAIT_ST();
        TC_FENCE_BEFORE();
        __syncthreads();

        // PV(it): O += P @ V   (issued now; executes while we stage next tiles)
        if (wid == 0 && elect1()) {
            TC_FENCE_AFTER();
            FENCE_ASYNC();
            uint64_t bd = MK_DESC(sb + AV + (it & 1) * 16384);
            #pragma unroll
            for (int ks = 0; ks < 8; ks++) {
                uint64_t off = (ks < 4) ? (uint64_t)(ks * 2) : (uint64_t)(512 + (ks - 4) * 2);
                mma_f16_ts(tb + 192, tb + 128 + ks * 8, bd + off, idpv, !(it == 0 && ks == 0));
            }
        }

        // stage K(it+1), V(it+1)
        if (it < 15) {
            const __half* kb = kball + (size_t)(it + 1) * 128 * 64;
            const __half* vt = vtall + (size_t)(it + 1) * 128;
            char* vbase = smem + AV + ((it + 1) & 1) * 16384;
            #pragma unroll
            for (int rep = 0; rep < 4; rep++) {
                int idx = tid + rep * 256;
                int nl = idx >> 3, j = idx & 7;
                uint4 kv = ((const uint4*)(kb + (size_t)nl * 64))[j];
                *(uint4*)(smem + AK + SWZ(nl * 128 + j * 16)) = kv;
                int d = idx >> 4, jj = idx & 15;
                uint4 vv = *(const uint4*)(vt + (size_t)d * N_ + jj * 8);
                uint32_t off = ((d >> 3) + (jj >> 3) * 8) * 1024 + (d & 7) * 128 + (jj & 7) * 16;
                *(uint4*)(vbase + SWZ(off)) = vv;
            }
        }
        TC_FENCE_BEFORE();
        __syncthreads();
        if (wid == 0 && elect1()) {
            TC_FENCE_AFTER();
            FENCE_ASYNC();
            if (it < 15) {
                uint64_t ad = MK_DESC(sb + AQ), bd = MK_DESC(sb + AK);
                #pragma unroll
                for (int ks = 0; ks < 4; ks++)
                    mma_f16_ss(tb, ad + ks * 2, bd + ks * 2, idq, ks > 0);
            }
            TC_COMMIT(sb + 8);
        }
    }
    MBAR_WAIT(sb + 8, ph);
    TC_FENCE_AFTER();

    // combine row sums across halves
    *(float*)(smem + APT + (half * 128 + row) * 4) = lsum;
    __syncthreads();

    if (tid < 128) {
        int orow = wid * 32 + lane;
        uint32_t o0[32], o1[32];
        LDTM_X32(o0, tb + 192);
        LDTM_X32(o1, tb + 224);
        TC_WAIT_LD();
        float rin = 1.f / (*(float*)(smem + APT + orow * 4)
                         + *(float*)(smem + APT + (128 + orow) * 4));
        float* od = g_x + (size_t)b * S_ * D_ + (size_t)(st * 128 + orow) * D_ + h * 64;
        #pragma unroll
        for (int j4 = 0; j4 < 8; j4++) {
            ((float4*)od)[j4] = make_float4(__uint_as_float(o0[j4 * 4 + 0]) * rin,
                                            __uint_as_float(o0[j4 * 4 + 1]) * rin,
                                            __uint_as_float(o0[j4 * 4 + 2]) * rin,
                                            __uint_as_float(o0[j4 * 4 + 3]) * rin);
            ((float4*)od)[8 + j4] = make_float4(__uint_as_float(o1[j4 * 4 + 0]) * rin,
                                                __uint_as_float(o1[j4 * 4 + 1]) * rin,
                                                __uint_as_float(o1[j4 * 4 + 2]) * rin,
                                                __uint_as_float(o1[j4 * 4 + 3]) * rin);
        }
    }
    TC_FENCE_BEFORE();
    __syncthreads();
    if (wid == 0) TC_DEALLOC(tb, 256);
#endif
}

// ---------------------------------------------------------------------------
// Kernel 3 (fast): LN over D fused to fp16 output g_xh
// ---------------------------------------------------------------------------
__global__ __launch_bounds__(256) void ln_fuse_kernel(
    const float* __restrict__ w, const float* __restrict__ bb)
{
    __shared__ float red[8];
    int row = blockIdx.x;
    int tid = threadIdx.x;
    float4 v = ((const float4*)(g_x + (size_t)row * D_))[tid];

    float s = v.x + v.y + v.z + v.w;
    #pragma unroll
    for (int off = 16; off; off >>= 1) s += __shfl_xor_sync(0xffffffffu, s, off);
    if ((tid & 31) == 0) red[tid >> 5] = s;
    __syncthreads();
    float tot = red[0] + red[1] + red[2] + red[3] + red[4] + red[5] + red[6] + red[7];
    float mean = tot * (1.f / D_);

    float dx = v.x - mean, dy = v.y - mean, dz = v.z - mean, dw = v.w - mean;
    float ss = dx * dx + dy * dy + dz * dz + dw * dw;
    __syncthreads();
    #pragma unroll
    for (int off = 16; off; off >>= 1) ss += __shfl_xor_sync(0xffffffffu, ss, off);
    if ((tid & 31) == 0) red[tid >> 5] = ss;
    __syncthreads();
    float vtot = red[0] + red[1] + red[2] + red[3] + red[4] + red[5] + red[6] + red[7];
    float inv = rsqrtf(vtot * (1.f / D_) + EPS_);

    float4 wv = ((const float4*)w)[tid];
    float4 bv = ((const float4*)bb)[tid];
    uint2 o;
    o.x = pack2h(dx * inv * wv.x + bv.x, dy * inv * wv.y + bv.y);
    o.y = pack2h(dz * inv * wv.z + bv.z, dw * inv * wv.w + bv.w);
    ((uint2*)(g_xh + (size_t)row * D_))[tid] = o;
}

// ---------------------------------------------------------------------------
// Kernel 4 (fast): fp16 tcgen05 GEMM  C = g_xh @ g_wh^T, 128x128 tiles, occ 2
// ---------------------------------------------------------------------------
#define GA 1024
#define GB 33792
#define GEMM_SMEM (33792 + 32768 + 256)

__global__ __launch_bounds__(256, 2) void gemm_tc_kernel(float* __restrict__ C)
{
#if HAS_TC
    extern __shared__ char smem[];
    uint32_t sb = smem_u32(smem);
    int tid = threadIdx.x, wid = tid >> 5, lane = tid & 31;
    int n0 = blockIdx.x * 128, m0 = blockIdx.y * 128;

    if (wid == 0) { TC_ALLOC(sb, 128); TC_RELINQ(); }
    if (tid == 0) { MBAR_INIT(sb + 8, 1); MBAR_INIT(sb + 16, 1); }
    __syncthreads();
    uint32_t tb;
    asm volatile("ld.shared.b32 %0, [%1];" : "=r"(tb) : "r"(sb));

    const uint32_t idc = IDESC_F16(128);
    int ph0 = 0, ph1 = 0;

    for (int c = 0; c < 16; c++) {
        int bs = c & 1;
        if (c >= 2) {
            if (bs == 0) { MBAR_WAIT(sb + 8, ph0);  ph0 ^= 1; }
            else         { MBAR_WAIT(sb + 16, ph1); ph1 ^= 1; }
        }
        int k0 = c * 64;
        char* abuf = smem + GA + bs * 16384;
        char* bbuf = smem + GB + bs * 16384;
        #pragma unroll
        for (int rep = 0; rep < 4; rep++) {
            int idx = tid + rep * 256;
            int r = idx >> 3, j = idx & 7;
            uint4 a4 = *(const uint4*)(g_xh + (size_t)(m0 + r) * D_ + k0 + j * 8);
            *(uint4*)(abuf + SWZ(r * 128 + j * 16)) = a4;
            uint4 b4 = *(const uint4*)(g_wh + (size_t)(n0 + r) * D_ + k0 + j * 8);
            *(uint4*)(bbuf + SWZ(r * 128 + j * 16)) = b4;
        }
        __syncthreads();
        if (wid == 0 && elect1()) {
            FENCE_ASYNC();
            uint64_t ad = MK_DESC(sb + GA + bs * 16384);
            uint64_t bd = MK_DESC(sb + GB + bs * 16384);
            #pragma unroll
            for (int ks = 0; ks < 4; ks++)
                mma_f16_ss(tb, ad + ks * 2, bd + ks * 2, idc, !(c == 0 && ks == 0));
            TC_COMMIT(sb + 8 + bs * 8);
        }
    }
    MBAR_WAIT(sb + 8, ph0);
    MBAR_WAIT(sb + 16, ph1);
    TC_FENCE_AFTER();

    int half = wid >> 2;
    int row = (wid & 3) * 32 + lane;
    uint32_t o0[32], o1[32];
    LDTM_X32(o0, tb + half * 64);
    LDTM_X32(o1, tb + half * 64 + 32);
    TC_WAIT_LD();
    float* cd = C + (size_t)(m0 + row) * D_ + n0 + half * 64;
    #pragma unroll
    for (int j4 = 0; j4 < 8; j4++) {
        ((float4*)cd)[j4] = make_float4(__uint_as_float(o0[j4 * 4 + 0]),
                                        __uint_as_float(o0[j4 * 4 + 1]),
                                        __uint_as_float(o0[j4 * 4 + 2]),
                                        __uint_as_float(o0[j4 * 4 + 3]));
        ((float4*)cd)[8 + j4] = make_float4(__uint_as_float(o1[j4 * 4 + 0]),
                                            __uint_as_float(o1[j4 * 4 + 1]),
                                            __uint_as_float(o1[j4 * 4 + 2]),
                                            __uint_as_float(o1[j4 * 4 + 3]));
    }
    TC_FENCE_BEFORE();
    __syncthreads();
    if (wid == 0) TC_DEALLOC(tb, 128);
#endif
}

// ---------------------------------------------------------------------------
// Fallback kernels (scalar path; only if sm_103a features absent)
// ---------------------------------------------------------------------------
#define ATTN_FB_SMEM ((4096 + 4160 + 4096 + 4096) * 4)

__global__ __launch_bounds__(256, 1) void attn_fb_kernel(
    const float* __restrict__ xq, const float* __restrict__ xv,
    const float* __restrict__ qnw, const float* __restrict__ qnb)
{
    extern __shared__ float sm[];
    float (*qs)[64] = (float(*)[64])(sm);
    float (*kt)[65] = (float(*)[65])(sm + 4096);
    float (*vs)[64] = (float(*)[64])(sm + 4096 + 4160);
    float (*ps)[64] = (float(*)[64])(sm + 4096 + 4160 + 4096);

    int b = blockIdx.z, h = blockIdx.y, st = blockIdx.x;
    int tid = threadIdx.x;
    int tx = tid & 15, ty = tid >> 4;

    const float* qbase = xq + (size_t)b * S_ * D_ + (size_t)h * S_ * HD_
                            + (size_t)st * 64 * HD_;
    for (int i = tid; i < 64 * 64; i += 256)
        qs[i >> 6][i & 63] = qbase[i];
    __syncthreads();

    if (tid < 64) {
        float m = 0.f;
        for (int d = 0; d < 64; d++) m += qs[tid][d];
        m *= (1.f / 64.f);
        float v = 0.f;
        for (int d = 0; d < 64; d++) { float t = qs[tid][d] - m; v += t * t; }
        float inv = rsqrtf(v * (1.f / 64.f) + EPS_);
        for (int d = 0; d < 64; d++)
            qs[tid][d] = ((qs[tid][d] - m) * inv * qnw[d] + qnb[d]) * 0.125f;
    }
    __syncthreads();

    float o[4][4] = {};
    float mrow[4] = {-INFINITY, -INFINITY, -INFINITY, -INFINITY};
    float lrow[4] = {};

    const __half* kb = g_kn + (size_t)b * N_ * HD_;
    const float* vb = xv + (size_t)b * N_ * HD_;

    for (int n0 = 0; n0 < N_; n0 += 64) {
        for (int i = tid; i < 64 * 64; i += 256) {
            int r = i >> 6, d = i & 63;
            kt[d][r] = __half2float(kb[(size_t)(n0 + r) * HD_ + d]);
            vs[r][d] = vb[(size_t)(n0 + r) * HD_ + d];
        }
        __syncthreads();

        float sc[4][4] = {};
        #pragma unroll 8
        for (int d = 0; d < 64; d++) {
            float qv[4], kv[4];
            #pragma unroll
            for (int i = 0; i < 4; i++) qv[i] = qs[ty * 4 + i][d];
            #pragma unroll
            for (int j = 0; j < 4; j++) kv[j] = kt[d][tx * 4 + j];
            #pragma unroll
            for (int i = 0; i < 4; i++)
                #pragma unroll
                for (int j = 0; j < 4; j++) sc[i][j] += qv[i] * kv[j];
        }

        #pragma unroll
        for (int i = 0; i < 4; i++) {
            float mx = fmaxf(fmaxf(sc[i][0], sc[i][1]), fmaxf(sc[i][2], sc[i][3]));
            #pragma unroll
            for (int off = 8; off; off >>= 1)
                mx = fmaxf(mx, __shfl_xor_sync(0xffffffffu, mx, off, 16));
            float mnew  = fmaxf(mrow[i], mx);
            float alpha = __expf(mrow[i] - mnew);
            float psum = 0.f;
            #pragma unroll
            for (int j = 0; j < 4; j++) {
                float p = __expf(sc[i][j] - mnew);
                ps[ty * 4 + i][tx * 4 + j] = p;
                psum += p;
            }
            #pragma unroll
            for (int off = 8; off; off >>= 1)
                psum += __shfl_xor_sync(0xffffffffu, psum, off, 16);
            lrow[i] = lrow[i] * alpha + psum;
            mrow[i] = mnew;
            #pragma unroll
            for (int j = 0; j < 4; j++) o[i][j] *= alpha;
        }
        __syncthreads();

        #pragma unroll 8
        for (int k = 0; k < 64; k++) {
            float pv[4], vv[4];
            #pragma unroll
            for (int i = 0; i < 4; i++) pv[i] = ps[ty * 4 + i][k];
            #pragma unroll
            for (int j = 0; j < 4; j++) vv[j] = vs[k][tx * 4 + j];
            #pragma unroll
            for (int i = 0; i < 4; i++)
                #pragma unroll
                for (int j = 0; j < 4; j++) o[i][j] += pv[i] * vv[j];
        }
        __syncthreads();
    }

    float* xo = g_x + (size_t)b * S_ * D_ + (size_t)(st * 64) * D_ + (size_t)h * 64;
    #pragma unroll
    for (int i = 0; i < 4; i++) {
        float rinv = 1.f / lrow[i];
        #pragma unroll
        for (int j = 0; j < 4; j++)
            xo[(size_t)(ty * 4 + i) * D_ + tx * 4 + j] = o[i][j] * rinv;
    }
}

__global__ __launch_bounds__(256) void ln_d_kernel(
    const float* __restrict__ w, const float* __restrict__ bb)
{
    __shared__ float red[8];
    int row = blockIdx.x;
    int tid = threadIdx.x;
    float4 v = ((const float4*)(g_x + (size_t)row * D_))[tid];

    float s = v.x + v.y + v.z + v.w;
    #pragma unroll
    for (int off = 16; off; off >>= 1) s += __shfl_xor_sync(0xffffffffu, s, off);
    if ((tid & 31) == 0) red[tid >> 5] = s;
    __syncthreads();
    float tot = red[0] + red[1] + red[2] + red[3] + red[4] + red[5] + red[6] + red[7];
    float mean = tot * (1.f / D_);
    float dx = v.x - mean, dy = v.y - mean, dz = v.z - mean, dw = v.w - mean;
    float ss = dx * dx + dy * dy + dz * dz + dw * dw;
    __syncthreads();
    #pragma unroll
    for (int off = 16; off; off >>= 1) ss += __shfl_xor_sync(0xffffffffu, ss, off);
    if ((tid & 31) == 0) red[tid >> 5] = ss;
    __syncthreads();
    float vtot = red[0] + red[1] + red[2] + red[3] + red[4] + red[5] + red[6] + red[7];
    float inv = rsqrtf(vtot * (1.f / D_) + EPS_);
    float4 wv = ((const float4*)w)[tid];
    float4 bv = ((const float4*)bb)[tid];
    float4 o;
    o.x = dx * inv * wv.x + bv.x;
    o.y = dy * inv * wv.y + bv.y;
    o.z = dz * inv * wv.z + bv.z;
    o.w = dw * inv * wv.w + bv.w;
    ((float4*)(g_xn + (size_t)row * D_))[tid] = o;
}

__global__ __launch_bounds__(256) void gemm_fb_kernel(
    const float* __restrict__ W, float* __restrict__ C)
{
    __shared__ float as[64][64];
    __shared__ float wt[64][65];
    int ct = blockIdx.x, rt = blockIdx.y;
    int tid = threadIdx.x, tx = tid & 15, ty = tid >> 4;
    float acc[4][4] = {};

    const float* Ab = g_xn + (size_t)rt * 64 * D_;
    const float* Wb = W    + (size_t)ct * 64 * D_;

    for (int k0 = 0; k0 < D_; k0 += 64) {
        for (int i = tid; i < 64 * 64; i += 256) {
            int r = i >> 6, k = i & 63;
            as[r][k] = Ab[(size_t)r * D_ + k0 + k];
            wt[k][r] = Wb[(size_t)r * D_ + k0 + k];
        }
        __syncthreads();
        #pragma unroll 8
        for (int k = 0; k < 64; k++) {
            float av[4], wv[4];
            #pragma unroll
            for (int i = 0; i < 4; i++) av[i] = as[ty * 4 + i][k];
            #pragma unroll
            for (int j = 0; j < 4; j++) wv[j] = wt[k][tx * 4 + j];
            #pragma unroll
            for (int i = 0; i < 4; i++)
                #pragma unroll
                for (int j = 0; j < 4; j++) acc[i][j] += av[i] * wv[j];
        }
        __syncthreads();
    }
    float* Cb = C + (size_t)(rt * 64) * D_ + ct * 64;
    #pragma unroll
    for (int i = 0; i < 4; i++)
        #pragma unroll
        for (int j = 0; j < 4; j++)
            Cb[(size_t)(ty * 4 + i) * D_ + tx * 4 + j] = acc[i][j];
}

// ---------------------------------------------------------------------------
extern "C" void kernel_launch(void* const* d_in, const int* in_sizes, int n_in,
                              void* d_out, int out_size)
{
    const float* x_q    = (const float*)d_in[0];
    const float* x_k    = (const float*)d_in[1];
    const float* x_v    = (const float*)d_in[2];
    const float* qn_w   = (const float*)d_in[3];
    const float* qn_b   = (const float*)d_in[4];
    const float* kn_w   = (const float*)d_in[5];
    const float* kn_b   = (const float*)d_in[6];
    const float* n_w    = (const float*)d_in[7];
    const float* n_b    = (const float*)d_in[8];
    const float* proj_w = (const float*)d_in[9];
    float* out = (float*)d_out;

    cudaFuncAttributes fa; fa.numRegs = 0;
    cudaFuncGetAttributes(&fa, attn_tc_kernel);
    bool fast = fa.numRegs >= 40;

    ln_k_kernel<<<(B_ * N_) / 8, 256>>>(x_k, kn_w, kn_b);

    if (fast) {
        cvt_v_kernel<<<dim3(N_ / 64, B_), 256>>>(x_v);
        cvt_w_kernel<<<(D_ * D_) / (256 * 8), 256>>>(proj_w);
        cudaFuncSetAttribute(attn_tc_kernel,
                             cudaFuncAttributeMaxDynamicSharedMemorySize, ATTN_SMEM);
        cudaFuncSetAttribute(gemm_tc_kernel,
                             cudaFuncAttributeMaxDynamicSharedMemorySize, GEMM_SMEM);
        attn_tc_kernel<<<dim3(S_ / 128, H_, B_), 256, ATTN_SMEM>>>(x_q, qn_w, qn_b);
        ln_fuse_kernel<<<B_ * S_, 256>>>(n_w, n_b);
        gemm_tc_kernel<<<dim3(D_ / 128, (B_ * S_) / 128), 256, GEMM_SMEM>>>(out);
    } else {
        cudaFuncSetAttribute(attn_fb_kernel,
                             cudaFuncAttributeMaxDynamicSharedMemorySize, ATTN_FB_SMEM);
        attn_fb_kernel<<<dim3(S_ / 64, H_, B_), 256, ATTN_FB_SMEM>>>(x_q, x_v, qn_w, qn_b);
        ln_d_kernel<<<B_ * S_, 256>>>(n_w, n_b);
        gemm_fb_kernel<<<dim3(D_ / 64, (B_ * S_) / 64), 256>>>(proj_w, out);
    }
}

// round 14
// speedup vs baseline: 12.1991x; 1.0701x over previous
#include <cuda_runtime.h>
#include <cuda_fp16.h>
#include <cstdint>
#include <math.h>

#define B_ 4
#define S_ 2048
#define N_ 2048
#define D_ 1024
#define H_ 16
#define HD_ 64
#define EPS_ 1e-5f

#ifndef __CUDA_ARCH__
  #define HAS_TC 1
#elif defined(__CUDA_ARCH_FEAT_SM103_ALL) || defined(__CUDA_ARCH_FEAT_SM100_ALL) || \
      defined(__CUDA_ARCH_FEAT_SM101_ALL)
  #define HAS_TC 1
#else
  #define HAS_TC 0
#endif

// Scratch
__device__ __half g_kn[B_ * N_ * HD_];                 // normalized K, fp16
__device__ __half g_vt[B_ * HD_ * N_];                 // V transposed [b][d][n], fp16
__device__ __half g_wh[D_ * D_];                       // proj_w fp16
__device__ float  g_x [(size_t)B_ * S_ * D_];          // attention out (B,S,D) fp32
__device__ __half g_xh[(size_t)B_ * S_ * D_];          // LN(x) fp16
__device__ float  g_xn[(size_t)B_ * S_ * D_];          // fallback only

// ---------------------------------------------------------------------------
// helpers
// ---------------------------------------------------------------------------
__device__ __forceinline__ uint32_t smem_u32(const void* p) {
    uint32_t a;
    asm("{ .reg .u64 t; cvta.to.shared.u64 t, %1; cvt.u32.u64 %0, t; }"
        : "=r"(a) : "l"(p));
    return a;
}
__device__ __forceinline__ uint32_t elect1() {
    uint32_t r;
    asm volatile("{ .reg .pred p; elect.sync _|p, 0xFFFFFFFF; selp.b32 %0, 1, 0, p; }"
                 : "=r"(r));
    return r;
}
__device__ __forceinline__ uint32_t pack2h(float a, float b) {
    __half2 h = __floats2half2_rn(a, b);
    return *reinterpret_cast<uint32_t*>(&h);
}
// result: low half = lo, high half = hi
__device__ __forceinline__ uint32_t cvt_f16x2(float hi, float lo) {
    uint32_t d;
    asm("cvt.rn.f16x2.f32 %0, %1, %2;" : "=r"(d) : "f"(hi), "f"(lo));
    return d;
}
__device__ __forceinline__ uint32_t ex2_f16x2(uint32_t x) {
    uint32_t d;
    asm("ex2.approx.f16x2 %0, %1;" : "=r"(d) : "r"(x));
    return d;
}

#define SWZ(x) ((uint32_t)(x) ^ ((((uint32_t)(x)) >> 3) & 0x70u))

static constexpr uint64_t DESC_BASE_SW128 =
    (uint64_t(2) << 61) | (uint64_t(1) << 46) | (uint64_t(64) << 32) | (uint64_t(1) << 16);
#define MK_DESC(addr) (DESC_BASE_SW128 | ((uint64_t)((addr) >> 4) & 0x3FFFull))

// idesc kind::f16 (fp16 in, fp32 accum): dtype F32=1 bit4, N/8 bit17, M=128 -> 8 bit24
#define IDESC_F16(Ncols) ((1u << 4) | (((Ncols) / 8u) << 17) | (8u << 24))

#if HAS_TC
__device__ __forceinline__ void mma_f16_ss(uint32_t d_tmem, uint64_t a_desc,
                                           uint64_t b_desc, uint32_t idesc, bool acc) {
    uint32_t en = acc ? 1u : 0u;
    asm volatile(
        "{\n\t.reg .pred p;\n\tsetp.ne.u32 p, %4, 0;\n\t"
        "tcgen05.mma.cta_group::1.kind::f16 [%0], %1, %2, %3, {%5, %5, %5, %5}, p;\n\t}"
        :: "r"(d_tmem), "l"(a_desc), "l"(b_desc), "r"(idesc), "r"(en), "r"(0u)
        : "memory");
}

#define TC_ALLOC(slot, n) \
    asm volatile("tcgen05.alloc.cta_group::1.sync.aligned.shared::cta.b32 [%0], %1;" \
                 :: "r"(slot), "r"((uint32_t)(n)) : "memory")
#define TC_RELINQ() \
    asm volatile("tcgen05.relinquish_alloc_permit.cta_group::1.sync.aligned;")
#define TC_DEALLOC(tb, n) \
    asm volatile("tcgen05.dealloc.cta_group::1.sync.aligned.b32 %0, %1;" :: "r"(tb), "r"((uint32_t)(n)))
#define TC_COMMIT(mbar) \
    asm volatile("tcgen05.commit.cta_group::1.mbarrier::arrive::one.shared::cluster.b64 [%0];" \
                 :: "r"(mbar) : "memory")
#define TC_FENCE_BEFORE() asm volatile("tcgen05.fence::before_thread_sync;" ::: "memory")
#define TC_FENCE_AFTER()  asm volatile("tcgen05.fence::after_thread_sync;" ::: "memory")
#define TC_WAIT_LD()      asm volatile("tcgen05.wait::ld.sync.aligned;" ::: "memory")
#define FENCE_ASYNC()     asm volatile("fence.proxy.async.shared::cta;" ::: "memory")

#define MBAR_INIT(a, c) \
    asm volatile("mbarrier.init.shared.b64 [%0], %1;" :: "r"(a), "r"((uint32_t)(c)) : "memory")
#define MBAR_WAIT(a, par) do { \
    uint32_t _m = (a); uint32_t _p = (par); uint32_t _d; \
    asm volatile("{\n\t.reg .pred p;\n\t" \
        "mbarrier.try_wait.parity.acquire.cta.shared::cta.b64 p, [%1], %2;\n\t" \
        "selp.b32 %0, 1, 0, p;\n\t}" : "=r"(_d) : "r"(_m), "r"(_p) : "memory"); \
    if (!_d) { \
        asm volatile("{\n\t.reg .pred P1;\n\tWL_%=:\n\t" \
            "mbarrier.try_wait.parity.acquire.cta.shared::cta.b64 P1, [%0], %1, 0x989680;\n\t" \
            "@P1 bra.uni WD_%=;\n\tbra.uni WL_%=;\n\tWD_%=:\n\t}" \
            :: "r"(_m), "r"(_p) : "memory"); \
    } } while (0)

#define LDTM_X32(r, a) \
    asm volatile("tcgen05.ld.sync.aligned.32x32b.x32.b32 " \
        "{%0,%1,%2,%3,%4,%5,%6,%7,%8,%9,%10,%11,%12,%13,%14,%15," \
        "%16,%17,%18,%19,%20,%21,%22,%23,%24,%25,%26,%27,%28,%29,%30,%31}, [%32];" \
        : "=r"((r)[0]), "=r"((r)[1]), "=r"((r)[2]), "=r"((r)[3]), \
          "=r"((r)[4]), "=r"((r)[5]), "=r"((r)[6]), "=r"((r)[7]), \
          "=r"((r)[8]), "=r"((r)[9]), "=r"((r)[10]), "=r"((r)[11]), \
          "=r"((r)[12]), "=r"((r)[13]), "=r"((r)[14]), "=r"((r)[15]), \
          "=r"((r)[16]), "=r"((r)[17]), "=r"((r)[18]), "=r"((r)[19]), \
          "=r"((r)[20]), "=r"((r)[21]), "=r"((r)[22]), "=r"((r)[23]), \
          "=r"((r)[24]), "=r"((r)[25]), "=r"((r)[26]), "=r"((r)[27]), \
          "=r"((r)[28]), "=r"((r)[29]), "=r"((r)[30]), "=r"((r)[31]) \
        : "r"(a))

#define LDTM_X4(r, a) \
    asm volatile("tcgen05.ld.sync.aligned.32x32b.x4.b32 {%0,%1,%2,%3}, [%4];" \
        : "=r"((r)[0]), "=r"((r)[1]), "=r"((r)[2]), "=r"((r)[3]) : "r"(a))
#endif

// ---------------------------------------------------------------------------
// Kernel 1: LayerNorm over K rows -> fp16 g_kn. One warp per row.
// ---------------------------------------------------------------------------
__global__ __launch_bounds__(256) void ln_k_kernel(
    const float* __restrict__ xk, const float* __restrict__ w,
    const float* __restrict__ bb)
{
    int row  = blockIdx.x * 8 + (threadIdx.x >> 5);
    int lane = threadIdx.x & 31;
    const float* r = xk + (size_t)row * HD_;
    float a0 = r[lane], a1 = r[lane + 32];
    float s = a0 + a1;
    #pragma unroll
    for (int off = 16; off; off >>= 1) s += __shfl_xor_sync(0xffffffffu, s, off);
    float mean = s * (1.f / 64.f);
    float d0 = a0 - mean, d1 = a1 - mean;
    float vv = d0 * d0 + d1 * d1;
    #pragma unroll
    for (int off = 16; off; off >>= 1) vv += __shfl_xor_sync(0xffffffffu, vv, off);
    float inv = rsqrtf(vv * (1.f / 64.f) + EPS_);
    g_kn[(size_t)row * HD_ + lane]      = __float2half_rn(d0 * inv * w[lane]      + bb[lane]);
    g_kn[(size_t)row * HD_ + lane + 32] = __float2half_rn(d1 * inv * w[lane + 32] + bb[lane + 32]);
}

// ---------------------------------------------------------------------------
// Kernel 1b: V transpose + fp16
// ---------------------------------------------------------------------------
__global__ __launch_bounds__(256) void cvt_v_kernel(const float* __restrict__ xv)
{
    __shared__ float t[64][65];
    int b = blockIdx.y, n0 = blockIdx.x * 64;
    int tid = threadIdx.x;
    #pragma unroll
    for (int rep = 0; rep < 4; rep++) {
        int idx = tid + rep * 256;
        int n = idx >> 4, j = idx & 15;
        float4 v = ((const float4*)(xv + (size_t)b * N_ * HD_ + (size_t)(n0 + n) * HD_))[j];
        t[n][j * 4 + 0] = v.x; t[n][j * 4 + 1] = v.y;
        t[n][j * 4 + 2] = v.z; t[n][j * 4 + 3] = v.w;
    }
    __syncthreads();
    int d = tid >> 2, g = tid & 3;
    uint32_t wds[8];
    #pragma unroll
    for (int m = 0; m < 8; m++)
        wds[m] = pack2h(t[g * 16 + 2 * m][d], t[g * 16 + 2 * m + 1][d]);
    __half* dst = g_vt + (size_t)b * HD_ * N_ + (size_t)d * N_ + n0 + g * 16;
    ((uint4*)dst)[0] = make_uint4(wds[0], wds[1], wds[2], wds[3]);
    ((uint4*)dst)[1] = make_uint4(wds[4], wds[5], wds[6], wds[7]);
}

// ---------------------------------------------------------------------------
// Kernel 1c: proj_w -> fp16
// ---------------------------------------------------------------------------
__global__ __launch_bounds__(256) void cvt_w_kernel(const float* __restrict__ W)
{
    int idx = blockIdx.x * 256 + threadIdx.x;
    const float4* src = (const float4*)(W) + idx * 2;
    float4 a = src[0], bq = src[1];
    ((uint4*)g_wh)[idx] = make_uint4(pack2h(a.x, a.y), pack2h(a.z, a.w),
                                     pack2h(bq.x, bq.y), pack2h(bq.z, bq.w));
}

// ---------------------------------------------------------------------------
// Kernel 2 (fast): tcgen05 fp16 attention. S holds t = s*log2e; P = exp2(t)
// via packed f16x2; row sums via ones-rows in V (PV N=72, O cols 64..71).
// SMEM: Q at 1024 (16K), K at 17408 (16K), P at 33792 (32K, 16 atom rows),
//       V two buffers of 18432 at 66560 (9 atom rows, rows 64..71 = ones).
// TMEM (256 cols): S fp32 at 0 (128), O fp32 at 128 (72).
// ---------------------------------------------------------------------------
#define AQ 1024
#define AK 17408
#define AP 33792
#define AV 66560
#define ATTN_SMEM (AV + 2 * 18432 + 128)

__global__ __launch_bounds__(256, 2) void attn_tc_kernel(
    const float* __restrict__ xq,
    const float* __restrict__ qnw, const float* __restrict__ qnb)
{
#if HAS_TC
    extern __shared__ char smem[];
    uint32_t sb = smem_u32(smem);
    int tid = threadIdx.x, wid = tid >> 5, lane = tid & 31;
    int b = blockIdx.z, h = blockIdx.y, st = blockIdx.x;

    if (wid == 0) { TC_ALLOC(sb, 256); TC_RELINQ(); }
    if (tid == 0) MBAR_INIT(sb + 8, 1);
    __syncthreads();
    uint32_t tb;
    asm volatile("ld.shared.b32 %0, [%1];" : "=r"(tb) : "r"(sb));

    const float QS = 0.125f * 1.44269504088896f;

    // Q load + LN (scaled) -> fp16 SMEM tile [128 x 64]
    if (tid < 128) {
        const float* qr = xq + (size_t)b * S_ * D_ + (size_t)h * S_ * HD_
                             + (size_t)(st * 128 + tid) * 64;
        float4 v[16];
        #pragma unroll
        for (int i = 0; i < 16; i++) v[i] = ((const float4*)qr)[i];
        float m = 0.f;
        #pragma unroll
        for (int i = 0; i < 16; i++) m += v[i].x + v[i].y + v[i].z + v[i].w;
        m *= (1.f / 64.f);
        float var = 0.f;
        #pragma unroll
        for (int i = 0; i < 16; i++) {
            float a = v[i].x - m, bq = v[i].y - m, c = v[i].z - m, d = v[i].w - m;
            var += a * a + bq * bq + c * c + d * d;
        }
        float inv = rsqrtf(var * (1.f / 64.f) + EPS_) * QS;
        uint32_t q[32];
        #pragma unroll
        for (int i = 0; i < 16; i++) {
            float4 w4 = ((const float4*)qnw)[i];
            float4 b4 = ((const float4*)qnb)[i];
            float x0 = (v[i].x - m) * inv * w4.x + b4.x * QS;
            float x1 = (v[i].y - m) * inv * w4.y + b4.y * QS;
            float x2 = (v[i].z - m) * inv * w4.z + b4.z * QS;
            float x3 = (v[i].w - m) * inv * w4.w + b4.w * QS;
            q[2 * i]     = pack2h(x0, x1);
            q[2 * i + 1] = pack2h(x2, x3);
        }
        #pragma unroll
        for (int j = 0; j < 8; j++)
            *(uint4*)(smem + AQ + SWZ(tid * 128 + j * 16)) =
                make_uint4(q[4 * j], q[4 * j + 1], q[4 * j + 2], q[4 * j + 3]);
    }

    // ones rows (rows 64..71) of both V buffers: atom index 8 and 17
    {
        int buf = tid >> 7, at = (tid >> 6) & 1, i = tid & 63;
        uint32_t one2 = 0x3C003C00u;
        *(uint4*)(smem + AV + buf * 18432 + (at ? 17408 : 8192) + i * 16) =
            make_uint4(one2, one2, one2, one2);
    }

    const uint32_t idq  = IDESC_F16(128);
    const uint32_t idpv = IDESC_F16(72);
    const __half* kball = g_kn + (size_t)b * N_ * HD_;
    const __half* vtall = g_vt + (size_t)b * HD_ * N_;

    // stage K(0), V(0)
    #pragma unroll
    for (int rep = 0; rep < 4; rep++) {
        int idx = tid + rep * 256;
        int nl = idx >> 3, j = idx & 7;
        uint4 kv = ((const uint4*)(kball + (size_t)nl * 64))[j];
        *(uint4*)(smem + AK + SWZ(nl * 128 + j * 16)) = kv;
        int d = idx >> 4, jj = idx & 15;
        uint4 vv = *(const uint4*)(vtall + (size_t)d * N_ + jj * 8);
        uint32_t off = ((d >> 3) + (jj >> 3) * 9) * 1024 + (d & 7) * 128 + (jj & 7) * 16;
        *(uint4*)(smem + AV + SWZ(off)) = vv;
    }
    __syncthreads();
    if (wid == 0 && elect1()) {
        FENCE_ASYNC();
        uint64_t ad = MK_DESC(sb + AQ), bd = MK_DESC(sb + AK);
        #pragma unroll
        for (int ks = 0; ks < 4; ks++)
            mma_f16_ss(tb, ad + ks * 2, bd + ks * 2, idq, ks > 0);
        TC_COMMIT(sb + 8);
    }

    int ph = 0;
    int half = wid >> 2;
    int m = (wid & 3) * 32 + lane;

    for (int it = 0; it < 16; it++) {
        MBAR_WAIT(sb + 8, ph); ph ^= 1;     // QK(it) done (and PV(it-1))
        TC_FENCE_AFTER();

        // stage K(it+1), V(it+1)
        if (it < 15) {
            const __half* kb = kball + (size_t)(it + 1) * 128 * 64;
            const __half* vt = vtall + (size_t)(it + 1) * 128;
            char* vbase = smem + AV + ((it + 1) & 1) * 18432;
            #pragma unroll
            for (int rep = 0; rep < 4; rep++) {
                int idx = tid + rep * 256;
                int nl = idx >> 3, j = idx & 7;
                uint4 kv = ((const uint4*)(kb + (size_t)nl * 64))[j];
                *(uint4*)(smem + AK + SWZ(nl * 128 + j * 16)) = kv;
                int d = idx >> 4, jj = idx & 15;
                uint4 vv = *(const uint4*)(vt + (size_t)d * N_ + jj * 8);
                uint32_t off = ((d >> 3) + (jj >> 3) * 9) * 1024 + (d & 7) * 128 + (jj & 7) * 16;
                *(uint4*)(vbase + SWZ(off)) = vv;
            }
        }

        // softmax: t (fp32 TMEM) -> P = exp2(t) packed fp16 -> SMEM
        {
            uint32_t r0[32], r1[32];
            LDTM_X32(r0, tb + half * 64);
            LDTM_X32(r1, tb + half * 64 + 32);
            TC_WAIT_LD();
            uint32_t pk[32];
            #pragma unroll
            for (int j = 0; j < 16; j++)
                pk[j] = ex2_f16x2(cvt_f16x2(__uint_as_float(r0[2 * j + 1]),
                                            __uint_as_float(r0[2 * j])));
            #pragma unroll
            for (int j = 0; j < 16; j++)
                pk[16 + j] = ex2_f16x2(cvt_f16x2(__uint_as_float(r1[2 * j + 1]),
                                                 __uint_as_float(r1[2 * j])));
            uint32_t prow = (m >> 3) * 1024 + half * 16384 + (m & 7) * 128;
            #pragma unroll
            for (int j = 0; j < 8; j++)
                *(uint4*)(smem + AP + SWZ(prow + j * 16)) =
                    make_uint4(pk[4 * j], pk[4 * j + 1], pk[4 * j + 2], pk[4 * j + 3]);
        }
        TC_FENCE_BEFORE();
        __syncthreads();

        if (wid == 0 && elect1()) {
            TC_FENCE_AFTER();
            FENCE_ASYNC();
            // PV(it): O[128,72] += P[128,128] x Vext[72,128]
            uint64_t ad = MK_DESC(sb + AP);
            uint64_t bd = MK_DESC(sb + AV + (it & 1) * 18432);
            #pragma unroll
            for (int ks = 0; ks < 8; ks++) {
                uint64_t ao = (ks < 4) ? (uint64_t)(ks * 2) : (uint64_t)(1024 + (ks - 4) * 2);
                uint64_t bo = (ks < 4) ? (uint64_t)(ks * 2) : (uint64_t)(576 + (ks - 4) * 2);
                mma_f16_ss(tb + 128, ad + ao, bd + bo, idpv, !(it == 0 && ks == 0));
            }
            if (it < 15) {
                uint64_t qd = MK_DESC(sb + AQ), kd = MK_DESC(sb + AK);
                #pragma unroll
                for (int ks = 0; ks < 4; ks++)
                    mma_f16_ss(tb, qd + ks * 2, kd + ks * 2, idq, ks > 0);
            }
            TC_COMMIT(sb + 8);
        }
    }
    MBAR_WAIT(sb + 8, ph);
    TC_FENCE_AFTER();

    // epilogue: divide O by row sums (O cols 64..71), write (B,S,D)
    if (tid < 128) {
        int orow = wid * 32 + lane;
        uint32_t o0[32], o1[32], l4[4];
        LDTM_X32(o0, tb + 128);
        LDTM_X32(o1, tb + 160);
        LDTM_X4(l4, tb + 192);
        TC_WAIT_LD();
        float rin = 1.f / __uint_as_float(l4[0]);
        float* od = g_x + (size_t)b * S_ * D_ + (size_t)(st * 128 + orow) * D_ + h * 64;
        #pragma unroll
        for (int j4 = 0; j4 < 8; j4++) {
            ((float4*)od)[j4] = make_float4(__uint_as_float(o0[j4 * 4 + 0]) * rin,
                                            __uint_as_float(o0[j4 * 4 + 1]) * rin,
                                            __uint_as_float(o0[j4 * 4 + 2]) * rin,
                                            __uint_as_float(o0[j4 * 4 + 3]) * rin);
            ((float4*)od)[8 + j4] = make_float4(__uint_as_float(o1[j4 * 4 + 0]) * rin,
                                                __uint_as_float(o1[j4 * 4 + 1]) * rin,
                                                __uint_as_float(o1[j4 * 4 + 2]) * rin,
                                                __uint_as_float(o1[j4 * 4 + 3]) * rin);
        }
    }
    TC_FENCE_BEFORE();
    __syncthreads();
    if (wid == 0) TC_DEALLOC(tb, 256);
#endif
}

// ---------------------------------------------------------------------------
// Kernel 3 (fast): LN over D fused to fp16 output g_xh
// ---------------------------------------------------------------------------
__global__ __launch_bounds__(256) void ln_fuse_kernel(
    const float* __restrict__ w, const float* __restrict__ bb)
{
    __shared__ float red[8];
    int row = blockIdx.x;
    int tid = threadIdx.x;
    float4 v = ((const float4*)(g_x + (size_t)row * D_))[tid];

    float s = v.x + v.y + v.z + v.w;
    #pragma unroll
    for (int off = 16; off; off >>= 1) s += __shfl_xor_sync(0xffffffffu, s, off);
    if ((tid & 31) == 0) red[tid >> 5] = s;
    __syncthreads();
    float tot = red[0] + red[1] + red[2] + red[3] + red[4] + red[5] + red[6] + red[7];
    float mean = tot * (1.f / D_);

    float dx = v.x - mean, dy = v.y - mean, dz = v.z - mean, dw = v.w - mean;
    float ss = dx * dx + dy * dy + dz * dz + dw * dw;
    __syncthreads();
    #pragma unroll
    for (int off = 16; off; off >>= 1) ss += __shfl_xor_sync(0xffffffffu, ss, off);
    if ((tid & 31) == 0) red[tid >> 5] = ss;
    __syncthreads();
    float vtot = red[0] + red[1] + red[2] + red[3] + red[4] + red[5] + red[6] + red[7];
    float inv = rsqrtf(vtot * (1.f / D_) + EPS_);

    float4 wv = ((const float4*)w)[tid];
    float4 bv = ((const float4*)bb)[tid];
    uint2 o;
    o.x = pack2h(dx * inv * wv.x + bv.x, dy * inv * wv.y + bv.y);
    o.y = pack2h(dz * inv * wv.z + bv.z, dw * inv * wv.w + bv.w);
    ((uint2*)(g_xh + (size_t)row * D_))[tid] = o;
}

// ---------------------------------------------------------------------------
// Kernel 4 (fast): fp16 tcgen05 GEMM with prefetched LDG pipeline, occ 2
// ---------------------------------------------------------------------------
#define GA 1024
#define GB 33792
#define GEMM_SMEM (33792 + 32768 + 256)

__global__ __launch_bounds__(256, 2) void gemm_tc_kernel(float* __restrict__ C)
{
#if HAS_TC
    extern __shared__ char smem[];
    uint32_t sb = smem_u32(smem);
    int tid = threadIdx.x, wid = tid >> 5, lane = tid & 31;
    int n0 = blockIdx.x * 128, m0 = blockIdx.y * 128;

    if (wid == 0) { TC_ALLOC(sb, 128); TC_RELINQ(); }
    if (tid == 0) { MBAR_INIT(sb + 8, 1); MBAR_INIT(sb + 16, 1); }
    __syncthreads();
    uint32_t tb;
    asm volatile("ld.shared.b32 %0, [%1];" : "=r"(tb) : "r"(sb));

    const uint32_t idc = IDESC_F16(128);
    int ph0 = 0, ph1 = 0;

    uint4 ra[4], rb[4];
    #pragma unroll
    for (int rep = 0; rep < 4; rep++) {
        int idx = tid + rep * 256;
        int r = idx >> 3, j = idx & 7;
        ra[rep] = *(const uint4*)(g_xh + (size_t)(m0 + r) * D_ + j * 8);
        rb[rep] = *(const uint4*)(g_wh + (size_t)(n0 + r) * D_ + j * 8);
    }

    for (int c = 0; c < 16; c++) {
        int bs = c & 1;
        if (c >= 2) {
            if (bs == 0) { MBAR_WAIT(sb + 8, ph0);  ph0 ^= 1; }
            else         { MBAR_WAIT(sb + 16, ph1); ph1 ^= 1; }
        }
        char* abuf = smem + GA + bs * 16384;
        char* bbuf = smem + GB + bs * 16384;
        #pragma unroll
        for (int rep = 0; rep < 4; rep++) {
            int idx = tid + rep * 256;
            int r = idx >> 3, j = idx & 7;
            *(uint4*)(abuf + SWZ(r * 128 + j * 16)) = ra[rep];
            *(uint4*)(bbuf + SWZ(r * 128 + j * 16)) = rb[rep];
        }
        if (c < 15) {
            int k0 = (c + 1) * 64;
            #pragma unroll
            for (int rep = 0; rep < 4; rep++) {
                int idx = tid + rep * 256;
                int r = idx >> 3, j = idx & 7;
                ra[rep] = *(const uint4*)(g_xh + (size_t)(m0 + r) * D_ + k0 + j * 8);
                rb[rep] = *(const uint4*)(g_wh + (size_t)(n0 + r) * D_ + k0 + j * 8);
            }
        }
        __syncthreads();
        if (wid == 0 && elect1()) {
            FENCE_ASYNC();
            uint64_t ad = MK_DESC(sb + GA + bs * 16384);
            uint64_t bd = MK_DESC(sb + GB + bs * 16384);
            #pragma unroll
            for (int ks = 0; ks < 4; ks++)
                mma_f16_ss(tb, ad + ks * 2, bd + ks * 2, idc, !(c == 0 && ks == 0));
            TC_COMMIT(sb + 8 + bs * 8);
        }
    }
    MBAR_WAIT(sb + 8, ph0);
    MBAR_WAIT(sb + 16, ph1);
    TC_FENCE_AFTER();

    int half = wid >> 2;
    int row = (wid & 3) * 32 + lane;
    uint32_t o0[32], o1[32];
    LDTM_X32(o0, tb + half * 64);
    LDTM_X32(o1, tb + half * 64 + 32);
    TC_WAIT_LD();
    float* cd = C + (size_t)(m0 + row) * D_ + n0 + half * 64;
    #pragma unroll
    for (int j4 = 0; j4 < 8; j4++) {
        ((float4*)cd)[j4] = make_float4(__uint_as_float(o0[j4 * 4 + 0]),
                                        __uint_as_float(o0[j4 * 4 + 1]),
                                        __uint_as_float(o0[j4 * 4 + 2]),
                                        __uint_as_float(o0[j4 * 4 + 3]));
        ((float4*)cd)[8 + j4] = make_float4(__uint_as_float(o1[j4 * 4 + 0]),
                                            __uint_as_float(o1[j4 * 4 + 1]),
                                            __uint_as_float(o1[j4 * 4 + 2]),
                                            __uint_as_float(o1[j4 * 4 + 3]));
    }
    TC_FENCE_BEFORE();
    __syncthreads();
    if (wid == 0) TC_DEALLOC(tb, 128);
#endif
}

// ---------------------------------------------------------------------------
// Fallback kernels (scalar path; only if sm_103a features absent)
// ---------------------------------------------------------------------------
#define ATTN_FB_SMEM ((4096 + 4160 + 4096 + 4096) * 4)

__global__ __launch_bounds__(256, 1) void attn_fb_kernel(
    const float* __restrict__ xq, const float* __restrict__ xv,
    const float* __restrict__ qnw, const float* __restrict__ qnb)
{
    extern __shared__ float sm[];
    float (*qs)[64] = (float(*)[64])(sm);
    float (*kt)[65] = (float(*)[65])(sm + 4096);
    float (*vs)[64] = (float(*)[64])(sm + 4096 + 4160);
    float (*ps)[64] = (float(*)[64])(sm + 4096 + 4160 + 4096);

    int b = blockIdx.z, h = blockIdx.y, st = blockIdx.x;
    int tid = threadIdx.x;
    int tx = tid & 15, ty = tid >> 4;

    const float* qbase = xq + (size_t)b * S_ * D_ + (size_t)h * S_ * HD_
                            + (size_t)st * 64 * HD_;
    for (int i = tid; i < 64 * 64; i += 256)
        qs[i >> 6][i & 63] = qbase[i];
    __syncthreads();

    if (tid < 64) {
        float m = 0.f;
        for (int d = 0; d < 64; d++) m += qs[tid][d];
        m *= (1.f / 64.f);
        float v = 0.f;
        for (int d = 0; d < 64; d++) { float t = qs[tid][d] - m; v += t * t; }
        float inv = rsqrtf(v * (1.f / 64.f) + EPS_);
        for (int d = 0; d < 64; d++)
            qs[tid][d] = ((qs[tid][d] - m) * inv * qnw[d] + qnb[d]) * 0.125f;
    }
    __syncthreads();

    float o[4][4] = {};
    float mrow[4] = {-INFINITY, -INFINITY, -INFINITY, -INFINITY};
    float lrow[4] = {};

    const __half* kb = g_kn + (size_t)b * N_ * HD_;
    const float* vb = xv + (size_t)b * N_ * HD_;

    for (int n0 = 0; n0 < N_; n0 += 64) {
        for (int i = tid; i < 64 * 64; i += 256) {
            int r = i >> 6, d = i & 63;
            kt[d][r] = __half2float(kb[(size_t)(n0 + r) * HD_ + d]);
            vs[r][d] = vb[(size_t)(n0 + r) * HD_ + d];
        }
        __syncthreads();

        float sc[4][4] = {};
        #pragma unroll 8
        for (int d = 0; d < 64; d++) {
            float qv[4], kv[4];
            #pragma unroll
            for (int i = 0; i < 4; i++) qv[i] = qs[ty * 4 + i][d];
            #pragma unroll
            for (int j = 0; j < 4; j++) kv[j] = kt[d][tx * 4 + j];
            #pragma unroll
            for (int i = 0; i < 4; i++)
                #pragma unroll
                for (int j = 0; j < 4; j++) sc[i][j] += qv[i] * kv[j];
        }

        #pragma unroll
        for (int i = 0; i < 4; i++) {
            float mx = fmaxf(fmaxf(sc[i][0], sc[i][1]), fmaxf(sc[i][2], sc[i][3]));
            #pragma unroll
            for (int off = 8; off; off >>= 1)
                mx = fmaxf(mx, __shfl_xor_sync(0xffffffffu, mx, off, 16));
            float mnew  = fmaxf(mrow[i], mx);
            float alpha = __expf(mrow[i] - mnew);
            float psum = 0.f;
            #pragma unroll
            for (int j = 0; j < 4; j++) {
                float p = __expf(sc[i][j] - mnew);
                ps[ty * 4 + i][tx * 4 + j] = p;
                psum += p;
            }
            #pragma unroll
            for (int off = 8; off; off >>= 1)
                psum += __shfl_xor_sync(0xffffffffu, psum, off, 16);
            lrow[i] = lrow[i] * alpha + psum;
            mrow[i] = mnew;
            #pragma unroll
            for (int j = 0; j < 4; j++) o[i][j] *= alpha;
        }
        __syncthreads();

        #pragma unroll 8
        for (int k = 0; k < 64; k++) {
            float pv[4], vv[4];
            #pragma unroll
            for (int i = 0; i < 4; i++) pv[i] = ps[ty * 4 + i][k];
            #pragma unroll
            for (int j = 0; j < 4; j++) vv[j] = vs[k][tx * 4 + j];
            #pragma unroll
            for (int i = 0; i < 4; i++)
                #pragma unroll
                for (int j = 0; j < 4; j++) o[i][j] += pv[i] * vv[j];
        }
        __syncthreads();
    }

    float* xo = g_x + (size_t)b * S_ * D_ + (size_t)(st * 64) * D_ + (size_t)h * 64;
    #pragma unroll
    for (int i = 0; i < 4; i++) {
        float rinv = 1.f / lrow[i];
        #pragma unroll
        for (int j = 0; j < 4; j++)
            xo[(size_t)(ty * 4 + i) * D_ + tx * 4 + j] = o[i][j] * rinv;
    }
}

__global__ __launch_bounds__(256) void ln_d_kernel(
    const float* __restrict__ w, const float* __restrict__ bb)
{
    __shared__ float red[8];
    int row = blockIdx.x;
    int tid = threadIdx.x;
    float4 v = ((const float4*)(g_x + (size_t)row * D_))[tid];

    float s = v.x + v.y + v.z + v.w;
    #pragma unroll
    for (int off = 16; off; off >>= 1) s += __shfl_xor_sync(0xffffffffu, s, off);
    if ((tid & 31) == 0) red[tid >> 5] = s;
    __syncthreads();
    float tot = red[0] + red[1] + red[2] + red[3] + red[4] + red[5] + red[6] + red[7];
    float mean = tot * (1.f / D_);
    float dx = v.x - mean, dy = v.y - mean, dz = v.z - mean, dw = v.w - mean;
    float ss = dx * dx + dy * dy + dz * dz + dw * dw;
    __syncthreads();
    #pragma unroll
    for (int off = 16; off; off >>= 1) ss += __shfl_xor_sync(0xffffffffu, ss, off);
    if ((tid & 31) == 0) red[tid >> 5] = ss;
    __syncthreads();
    float vtot = red[0] + red[1] + red[2] + red[3] + red[4] + red[5] + red[6] + red[7];
    float inv = rsqrtf(vtot * (1.f / D_) + EPS_);
    float4 wv = ((const float4*)w)[tid];
    float4 bv = ((const float4*)bb)[tid];
    float4 o;
    o.x = dx * inv * wv.x + bv.x;
    o.y = dy * inv * wv.y + bv.y;
    o.z = dz * inv * wv.z + bv.z;
    o.w = dw * inv * wv.w + bv.w;
    ((float4*)(g_xn + (size_t)row * D_))[tid] = o;
}

__global__ __launch_bounds__(256) void gemm_fb_kernel(
    const float* __restrict__ W, float* __restrict__ C)
{
    __shared__ float as[64][64];
    __shared__ float wt[64][65];
    int ct = blockIdx.x, rt = blockIdx.y;
    int tid = threadIdx.x, tx = tid & 15, ty = tid >> 4;
    float acc[4][4] = {};

    const float* Ab = g_xn + (size_t)rt * 64 * D_;
    const float* Wb = W    + (size_t)ct * 64 * D_;

    for (int k0 = 0; k0 < D_; k0 += 64) {
        for (int i = tid; i < 64 * 64; i += 256) {
            int r = i >> 6, k = i & 63;
            as[r][k] = Ab[(size_t)r * D_ + k0 + k];
            wt[k][r] = Wb[(size_t)r * D_ + k0 + k];
        }
        __syncthreads();
        #pragma unroll 8
        for (int k = 0; k < 64; k++) {
            float av[4], wv[4];
            #pragma unroll
            for (int i = 0; i < 4; i++) av[i] = as[ty * 4 + i][k];
            #pragma unroll
            for (int j = 0; j < 4; j++) wv[j] = wt[k][tx * 4 + j];
            #pragma unroll
            for (int i = 0; i < 4; i++)
                #pragma unroll
                for (int j = 0; j < 4; j++) acc[i][j] += av[i] * wv[j];
        }
        __syncthreads();
    }
    float* Cb = C + (size_t)(rt * 64) * D_ + ct * 64;
    #pragma unroll
    for (int i = 0; i < 4; i++)
        #pragma unroll
        for (int j = 0; j < 4; j++)
            Cb[(size_t)(ty * 4 + i) * D_ + tx * 4 + j] = acc[i][j];
}

// ---------------------------------------------------------------------------
extern "C" void kernel_launch(void* const* d_in, const int* in_sizes, int n_in,
                              void* d_out, int out_size)
{
    const float* x_q    = (const float*)d_in[0];
    const float* x_k    = (const float*)d_in[1];
    const float* x_v    = (const float*)d_in[2];
    const float* qn_w   = (const float*)d_in[3];
    const float* qn_b   = (const float*)d_in[4];
    const float* kn_w   = (const float*)d_in[5];
    const float* kn_b   = (const float*)d_in[6];
    const float* n_w    = (const float*)d_in[7];
    const float* n_b    = (const float*)d_in[8];
    const float* proj_w = (const float*)d_in[9];
    float* out = (float*)d_out;

    cudaFuncAttributes fa; fa.numRegs = 0;
    cudaFuncGetAttributes(&fa, attn_tc_kernel);
    bool fast = fa.numRegs >= 40;

    ln_k_kernel<<<(B_ * N_) / 8, 256>>>(x_k, kn_w, kn_b);

    if (fast) {
        cvt_v_kernel<<<dim3(N_ / 64, B_), 256>>>(x_v);
        cvt_w_kernel<<<(D_ * D_) / (256 * 8), 256>>>(proj_w);
        cudaFuncSetAttribute(attn_tc_kernel,
                             cudaFuncAttributeMaxDynamicSharedMemorySize, ATTN_SMEM);
        cudaFuncSetAttribute(gemm_tc_kernel,
                             cudaFuncAttributeMaxDynamicSharedMemorySize, GEMM_SMEM);
        attn_tc_kernel<<<dim3(S_ / 128, H_, B_), 256, ATTN_SMEM>>>(x_q, qn_w, qn_b);
        ln_fuse_kernel<<<B_ * S_, 256>>>(n_w, n_b);
        gemm_tc_kernel<<<dim3(D_ / 128, (B_ * S_) / 128), 256, GEMM_SMEM>>>(out);
    } else {
        cudaFuncSetAttribute(attn_fb_kernel,
                             cudaFuncAttributeMaxDynamicSharedMemorySize, ATTN_FB_SMEM);
        attn_fb_kernel<<<dim3(S_ / 64, H_, B_), 256, ATTN_FB_SMEM>>>(x_q, x_v, qn_w, qn_b);
        ln_d_kernel<<<B_ * S_, 256>>>(n_w, n_b);
        gemm_fb_kernel<<<dim3(D_ / 64, (B_ * S_) / 64), 256>>>(proj_w, out);
    }
}